// round 1
// baseline (speedup 1.0000x reference)
#include <cuda_runtime.h>

#define Gn 512
#define An 24
#define Hd 128
#define NN (Gn*An)
#define NLAYER 4
#define EINW 325

// dynamic smem for edge kernel (floats):
// W2 16384 | Wd 7680 | P 3072 | Q 3072 | S 720 | C 720 | lat 128 | b2 128
// | fdemb 2880 | u 6144 | part 1024  = 41952 floats
#define EDGE_SMEM_FLOATS 41952
#define EDGE_SMEM_BYTES (EDGE_SMEM_FLOATS*4)

// ---------------- scratch (static device allocations, allowed) -------------
__device__ float d_h[NN*Hd];
__device__ float d_P[NN*Hd];
__device__ float d_Q[NN*Hd];
__device__ float d_agg[NN*Hd];
__device__ float d_ts[NN*30];
__device__ float d_tc[NN*30];
__device__ float d_latips[Gn*9];
__device__ float d_latC[Gn*Hd];

__device__ __forceinline__ float silu_f(float x){
    return __fdividef(x, 1.0f + __expf(-x));
}

// ---------------- per-node trig tables --------------------------------------
__global__ void trig_kernel(const float* __restrict__ frac){
    int idx = blockIdx.x*blockDim.x + threadIdx.x;
    if (idx >= NN*30) return;
    int n = idx/30; int r = idx - n*30; int dd = r/10; int f = r - dd*10;
    float x = frac[n*3+dd];
    float th = 6.283185307179586f * (float)f * x;
    d_ts[idx] = sinf(th);
    d_tc[idx] = cosf(th);
}

// ---------------- latent: h0 = [emb | t | xrd] @ latent_w + b ---------------
__global__ void __launch_bounds__(256) latent_kernel(
    const float* __restrict__ t, const int* __restrict__ atom_types,
    const int* __restrict__ node2graph, const float* __restrict__ xrd,
    const float* __restrict__ emb, const float* __restrict__ lw,
    const float* __restrict__ lb)
{
    __shared__ float sW[64*Hd];   // 32 KB
    __shared__ float sX[48*64];   // 12 KB
    int n0 = blockIdx.x*48;
    int tx = threadIdx.x;
    int warp = tx>>5, lane = tx&31, c0 = lane*4;
    float acc[6][4];
    #pragma unroll
    for (int e=0;e<6;e++){
        #pragma unroll
        for (int q=0;q<4;q++) acc[e][q] = lb[c0+q];
    }
    for (int kc=0;kc<6;kc++){
        for (int idx=tx; idx<64*Hd; idx+=256) sW[idx] = lw[kc*64*Hd + idx];
        for (int idx=tx; idx<48*64; idx+=256){
            int nl = idx>>6; int kk = idx&63; int k = kc*64+kk; int n = n0+nl;
            float v;
            if (k < 128)      v = emb[(atom_types[n]-1)*Hd + k];
            else if (k < 256) v = t[node2graph[n]*Hd + (k-128)];
            else              v = xrd[node2graph[n]*Hd + (k-256)];
            sX[idx] = v;
        }
        __syncthreads();
        #pragma unroll 4
        for (int kk=0;kk<64;kk++){
            float4 w4 = *(const float4*)&sW[kk*Hd + c0];
            #pragma unroll
            for (int e=0;e<6;e++){
                float xv = sX[(warp*6+e)*64 + kk];
                acc[e][0] += xv*w4.x; acc[e][1] += xv*w4.y;
                acc[e][2] += xv*w4.z; acc[e][3] += xv*w4.w;
            }
        }
        __syncthreads();
    }
    #pragma unroll
    for (int e=0;e<6;e++){
        float4 o = make_float4(acc[e][0],acc[e][1],acc[e][2],acc[e][3]);
        *(float4*)&d_h[(n0+warp*6+e)*Hd + c0] = o;
    }
}

// ---------------- lattice inner products ------------------------------------
__global__ void latips_kernel(const float* __restrict__ lat){
    int idx = blockIdx.x*blockDim.x + threadIdx.x;
    if (idx >= Gn*9) return;
    int g = idx/9; int rs = idx - g*9; int r = rs/3; int s = rs - r*3;
    const float* Lg = lat + g*9;
    d_latips[idx] = Lg[r*3]*Lg[s*3] + Lg[r*3+1]*Lg[s*3+1] + Lg[r*3+2]*Lg[s*3+2];
}

// ---------------- per-layer lattice projection (+ fold edge_b1) -------------
__global__ void latC_kernel(const float* __restrict__ ew1,
                            const float* __restrict__ eb1, int l){
    int g = blockIdx.x; int c = threadIdx.x;
    float acc = eb1[l*Hd + c];
    const float* wc = ew1 + (l*EINW + 256)*Hd;
    #pragma unroll
    for (int k=0;k<9;k++) acc += d_latips[g*9+k] * wc[k*Hd + c];
    d_latC[g*Hd + c] = acc;
}

// ---------------- per-layer node projections P = h@Wa, Q = h@Wb -------------
__global__ void __launch_bounds__(256) nodeproj_kernel(const float* __restrict__ ew1, int l){
    __shared__ float shT[Hd*24];
    int g = blockIdx.x; int tx = threadIdx.x;
    for (int idx=tx; idx<24*Hd; idx+=256){
        int nl = idx>>7; int k = idx&127;
        shT[k*24+nl] = d_h[(g*24+nl)*Hd + k];
    }
    __syncthreads();
    int c = tx&127; int half = tx>>7;
    const float* W = ew1 + (l*EINW + half*Hd)*Hd;
    float acc[24];
    #pragma unroll
    for (int j=0;j<24;j++) acc[j] = 0.f;
    #pragma unroll 4
    for (int k=0;k<Hd;k++){
        float w = W[k*Hd + c];
        #pragma unroll
        for (int jb=0;jb<6;jb++){
            float4 hv = *(const float4*)&shT[k*24 + jb*4];
            acc[jb*4+0] += hv.x*w; acc[jb*4+1] += hv.y*w;
            acc[jb*4+2] += hv.z*w; acc[jb*4+3] += hv.w*w;
        }
    }
    float* out = half ? d_Q : d_P;
    #pragma unroll
    for (int j=0;j<24;j++) out[(g*24+j)*Hd + c] = acc[j];
}

// ---------------- the hot kernel: edge MLP + scatter-mean per graph ---------
__global__ void __launch_bounds__(256) edge_kernel(
    const float* __restrict__ ew1, const float* __restrict__ ew2,
    const float* __restrict__ eb2, int l)
{
    extern __shared__ float sm[];
    float* sW2   = sm;               // 16384
    float* sWd   = sW2 + 16384;      // 7680
    float* sP    = sWd + 7680;       // 3072
    float* sQ    = sP  + 3072;       // 3072
    float* sS    = sQ  + 3072;       // 720
    float* sC    = sS  + 720;        // 720
    float* sLat  = sC  + 720;        // 128
    float* sB2   = sLat + 128;       // 128
    float* sFd   = sB2 + 128;        // 2880 (48 x 60)
    float* sU    = sFd + 2880;       // 6144 (48 x 128)
    float* sPart = sU  + 6144;       // 1024 (8 warps x 128)

    int g = blockIdx.x;
    int tx = threadIdx.x;
    const float* w2 = ew2 + l*Hd*Hd;
    const float* wd = ew1 + (l*EINW + 265)*Hd;
    for (int idx=tx; idx<Hd*Hd; idx+=256) sW2[idx] = w2[idx];
    for (int idx=tx; idx<60*Hd; idx+=256) sWd[idx] = wd[idx];
    for (int idx=tx; idx<24*Hd; idx+=256){
        sP[idx] = d_P[g*24*Hd + idx];
        sQ[idx] = d_Q[g*24*Hd + idx];
    }
    for (int idx=tx; idx<720; idx+=256){
        sS[idx] = d_ts[g*720 + idx];
        sC[idx] = d_tc[g*720 + idx];
    }
    if (tx < 128){ sLat[tx] = d_latC[g*Hd+tx]; sB2[tx] = eb2[l*Hd+tx]; }
    __syncthreads();

    int warp = tx>>5, lane = tx&31, c0 = lane*4;
    int ebase = warp*6;

    for (int it=0; it<12; ++it){
        int i0 = it*2;
        // ---- phase 0: fdemb for the 48 edges of this src pair ----
        for (int idx=tx; idx<48*60; idx+=256){
            int e = idx/60; int k = idx - e*60;
            int i = i0 + (e>=24 ? 1 : 0);
            int j = (e>=24) ? e-24 : e;
            int df = (k<30) ? k : k-30;
            float sj = sS[j*30+df], cj = sC[j*30+df];
            float si = sS[i*30+df], ci = sC[i*30+df];
            sFd[idx] = (k<30) ? (sj*ci - cj*si) : (cj*ci + sj*si);
        }
        __syncthreads();
        // ---- phase A: u = silu(P[src]+Q[dst]+latC+fd@Wd) ----
        {
            float acc[6][4];
            #pragma unroll
            for (int e6=0;e6<6;e6++){
                int e = ebase+e6;
                int i = i0 + (e>=24 ? 1 : 0);
                int j = (e>=24) ? e-24 : e;
                #pragma unroll
                for (int q=0;q<4;q++)
                    acc[e6][q] = sP[i*Hd+c0+q] + sQ[j*Hd+c0+q] + sLat[c0+q];
            }
            for (int k=0;k<60;k+=4){
                float4 w0 = *(const float4*)&sWd[(k+0)*Hd+c0];
                float4 w1 = *(const float4*)&sWd[(k+1)*Hd+c0];
                float4 w2v= *(const float4*)&sWd[(k+2)*Hd+c0];
                float4 w3 = *(const float4*)&sWd[(k+3)*Hd+c0];
                #pragma unroll
                for (int e6=0;e6<6;e6++){
                    float4 f4 = *(const float4*)&sFd[(ebase+e6)*60 + k];
                    acc[e6][0] += f4.x*w0.x; acc[e6][0] += f4.y*w1.x;
                    acc[e6][0] += f4.z*w2v.x; acc[e6][0] += f4.w*w3.x;
                    acc[e6][1] += f4.x*w0.y; acc[e6][1] += f4.y*w1.y;
                    acc[e6][1] += f4.z*w2v.y; acc[e6][1] += f4.w*w3.y;
                    acc[e6][2] += f4.x*w0.z; acc[e6][2] += f4.y*w1.z;
                    acc[e6][2] += f4.z*w2v.z; acc[e6][2] += f4.w*w3.z;
                    acc[e6][3] += f4.x*w0.w; acc[e6][3] += f4.y*w1.w;
                    acc[e6][3] += f4.z*w2v.w; acc[e6][3] += f4.w*w3.w;
                }
            }
            #pragma unroll
            for (int e6=0;e6<6;e6++){
                float4 o;
                o.x = silu_f(acc[e6][0]); o.y = silu_f(acc[e6][1]);
                o.z = silu_f(acc[e6][2]); o.w = silu_f(acc[e6][3]);
                *(float4*)&sU[(ebase+e6)*Hd + c0] = o;
            }
        }
        __syncthreads();
        // ---- phase B: ef = silu(u@W2+b2), partial-reduce over dsts ----
        {
            float dv[6][4];
            #pragma unroll
            for (int e6=0;e6<6;e6++){
                #pragma unroll
                for (int q=0;q<4;q++) dv[e6][q] = sB2[c0+q];
            }
            for (int k=0;k<Hd;k+=4){
                float4 w0 = *(const float4*)&sW2[(k+0)*Hd+c0];
                float4 w1 = *(const float4*)&sW2[(k+1)*Hd+c0];
                float4 w2v= *(const float4*)&sW2[(k+2)*Hd+c0];
                float4 w3 = *(const float4*)&sW2[(k+3)*Hd+c0];
                #pragma unroll
                for (int e6=0;e6<6;e6++){
                    float4 u4 = *(const float4*)&sU[(ebase+e6)*Hd + k];
                    dv[e6][0] += u4.x*w0.x; dv[e6][0] += u4.y*w1.x;
                    dv[e6][0] += u4.z*w2v.x; dv[e6][0] += u4.w*w3.x;
                    dv[e6][1] += u4.x*w0.y; dv[e6][1] += u4.y*w1.y;
                    dv[e6][1] += u4.z*w2v.y; dv[e6][1] += u4.w*w3.y;
                    dv[e6][2] += u4.x*w0.z; dv[e6][2] += u4.y*w1.z;
                    dv[e6][2] += u4.z*w2v.z; dv[e6][2] += u4.w*w3.z;
                    dv[e6][3] += u4.x*w0.w; dv[e6][3] += u4.y*w1.w;
                    dv[e6][3] += u4.z*w2v.w; dv[e6][3] += u4.w*w3.w;
                }
            }
            float p0=0.f,p1=0.f,p2=0.f,p3=0.f;
            #pragma unroll
            for (int e6=0;e6<6;e6++){
                p0 += silu_f(dv[e6][0]); p1 += silu_f(dv[e6][1]);
                p2 += silu_f(dv[e6][2]); p3 += silu_f(dv[e6][3]);
            }
            *(float4*)&sPart[warp*Hd + c0] = make_float4(p0,p1,p2,p3);
        }
        __syncthreads();
        {
            int sslot = tx>>7; int c = tx&127;
            float s = sPart[(sslot*4+0)*Hd+c] + sPart[(sslot*4+1)*Hd+c]
                    + sPart[(sslot*4+2)*Hd+c] + sPart[(sslot*4+3)*Hd+c];
            d_agg[(g*24 + i0 + sslot)*Hd + c] = s * (1.0f/24.0f);
        }
        __syncthreads();
    }
}

// ---------------- per-layer node MLP + residual -----------------------------
__global__ void __launch_bounds__(256) nodemlp_kernel(
    const float* __restrict__ nw1, const float* __restrict__ nb1,
    const float* __restrict__ nw2, const float* __restrict__ nb2, int l)
{
    __shared__ float xT[256*24];   // 24 KB
    __shared__ float y1T[Hd*24];   // 12 KB
    int g = blockIdx.x; int tx = threadIdx.x;
    for (int idx=tx; idx<24*Hd; idx+=256){
        int nl = idx>>7; int k = idx&127;
        xT[k*24+nl]       = d_h[(g*24+nl)*Hd + k];
        xT[(128+k)*24+nl] = d_agg[(g*24+nl)*Hd + k];
    }
    __syncthreads();
    int c = tx&127; int jh = tx>>7; int jbase = jh*12;
    const float* W1 = nw1 + l*256*Hd;
    float acc[12];
    #pragma unroll
    for (int j=0;j<12;j++) acc[j] = 0.f;
    #pragma unroll 4
    for (int k=0;k<256;k++){
        float w = W1[k*Hd + c];
        #pragma unroll
        for (int jb=0;jb<3;jb++){
            float4 hv = *(const float4*)&xT[k*24 + jbase + jb*4];
            acc[jb*4+0] += hv.x*w; acc[jb*4+1] += hv.y*w;
            acc[jb*4+2] += hv.z*w; acc[jb*4+3] += hv.w*w;
        }
    }
    float b1 = nb1[l*Hd + c];
    #pragma unroll
    for (int j=0;j<12;j++) y1T[c*24 + jbase + j] = silu_f(acc[j] + b1);
    __syncthreads();
    const float* W2 = nw2 + l*Hd*Hd;
    float acc2[12];
    #pragma unroll
    for (int j=0;j<12;j++) acc2[j] = 0.f;
    #pragma unroll 4
    for (int k=0;k<Hd;k++){
        float w = W2[k*Hd + c];
        #pragma unroll
        for (int jb=0;jb<3;jb++){
            float4 yv = *(const float4*)&y1T[k*24 + jbase + jb*4];
            acc2[jb*4+0] += yv.x*w; acc2[jb*4+1] += yv.y*w;
            acc2[jb*4+2] += yv.z*w; acc2[jb*4+3] += yv.w*w;
        }
    }
    float b2v = nb2[l*Hd + c];
    #pragma unroll
    for (int j=0;j<12;j++){
        float o = silu_f(acc2[j] + b2v);
        d_h[(g*24 + jbase + j)*Hd + c] += o;
    }
}

// ---------------- final heads -----------------------------------------------
__global__ void __launch_bounds__(128) final_kernel(
    const float* __restrict__ lat, const float* __restrict__ cw,
    const float* __restrict__ lw, float* __restrict__ out)
{
    __shared__ float sh[24*Hd];
    __shared__ float sgf[Hd];
    __shared__ float smid[9];
    __shared__ float scw[Hd*3];
    int g = blockIdx.x; int tx = threadIdx.x;
    for (int idx=tx; idx<24*Hd; idx+=128) sh[idx] = d_h[g*24*Hd + idx];
    for (int idx=tx; idx<Hd*3; idx+=128) scw[idx] = cw[idx];
    __syncthreads();
    {
        float acc = 0.f;
        #pragma unroll
        for (int a=0;a<24;a++) acc += sh[a*Hd + tx];
        sgf[tx] = acc * (1.0f/24.0f);
    }
    if (tx < 72){
        int n = tx/3; int dd = tx - n*3;
        float s = 0.f;
        #pragma unroll 4
        for (int k=0;k<Hd;k++) s += sh[n*Hd+k]*scw[k*3+dd];
        out[Gn*9 + (g*24+n)*3 + dd] = s;
    }
    __syncthreads();
    if (tx < 9){
        float s = 0.f;
        #pragma unroll 4
        for (int k=0;k<Hd;k++) s += sgf[k]*lw[k*9+tx];
        smid[tx] = s;
    }
    __syncthreads();
    if (tx < 9){
        int r = tx/3; int sc = tx - r*3;
        const float* Lg = lat + g*9;
        out[g*9+tx] = smid[r*3+0]*Lg[0+sc] + smid[r*3+1]*Lg[3+sc]
                    + smid[r*3+2]*Lg[6+sc];
    }
}

// ---------------- launch ----------------------------------------------------
extern "C" void kernel_launch(void* const* d_in, const int* in_sizes, int n_in,
                              void* d_out, int out_size)
{
    const float* t          = (const float*)d_in[0];
    const int*   atom_types = (const int*)  d_in[1];
    const float* frac       = (const float*)d_in[2];
    const float* lattices   = (const float*)d_in[3];
    // d_in[4] num_atoms: constant 24, unused
    const int*   node2graph = (const int*)  d_in[5];
    const float* xrd        = (const float*)d_in[6];
    const float* emb        = (const float*)d_in[7];
    const float* latent_w   = (const float*)d_in[8];
    const float* latent_b   = (const float*)d_in[9];
    const float* edge_w1    = (const float*)d_in[10];
    const float* edge_b1    = (const float*)d_in[11];
    const float* edge_w2    = (const float*)d_in[12];
    const float* edge_b2    = (const float*)d_in[13];
    const float* node_w1    = (const float*)d_in[14];
    const float* node_b1    = (const float*)d_in[15];
    const float* node_w2    = (const float*)d_in[16];
    const float* node_b2    = (const float*)d_in[17];
    const float* coord_w    = (const float*)d_in[18];
    const float* lattice_w  = (const float*)d_in[19];
    float* out = (float*)d_out;

    cudaFuncSetAttribute(edge_kernel,
        cudaFuncAttributeMaxDynamicSharedMemorySize, EDGE_SMEM_BYTES);

    trig_kernel<<<(NN*30 + 255)/256, 256>>>(frac);
    latent_kernel<<<NN/48, 256>>>(t, atom_types, node2graph, xrd,
                                  emb, latent_w, latent_b);
    latips_kernel<<<(Gn*9 + 255)/256, 256>>>(lattices);

    for (int l=0; l<NLAYER; ++l){
        latC_kernel<<<Gn, 128>>>(edge_w1, edge_b1, l);
        nodeproj_kernel<<<Gn, 256>>>(edge_w1, l);
        edge_kernel<<<Gn, 256, EDGE_SMEM_BYTES>>>(edge_w1, edge_w2, edge_b2, l);
        nodemlp_kernel<<<Gn, 256>>>(node_w1, node_b1, node_w2, node_b2, l);
    }

    final_kernel<<<Gn, 128>>>(lattices, coord_w, lattice_w, out);
}

// round 2
// speedup vs baseline: 1.8228x; 1.8228x over previous
#include <cuda_runtime.h>

#define Gn 512
#define An 24
#define Hd 128
#define NN (Gn*An)
#define NLAYER 4
#define EINW 325

// edge kernel dynamic smem layout (floats):
// sW2u 17408 | sWdu 8704 | sUu 12672 | sFdu 6528 | sP 3072 | sQ 3072
// | sS 720 | sC 720 | sLat 128 | sB2 128  = 53152 floats (212608 B)
#define EDGE_SMEM_FLOATS 53152
#define EDGE_SMEM_BYTES (EDGE_SMEM_FLOATS*4)

// ---------------- scratch (static device arrays, allowed) -------------------
__device__ float d_h[NN*Hd];
__device__ float d_P[NN*Hd];
__device__ float d_Q[NN*Hd];
__device__ float d_agg[NN*Hd];
__device__ float d_ts[NN*30];
__device__ float d_tc[NN*30];
__device__ float d_latips[Gn*9];
__device__ float d_latC[Gn*Hd];

__device__ __forceinline__ float silu_f(float x){
    return __fdividef(x, 1.0f + __expf(-x));
}

__device__ __forceinline__ unsigned tf32_rna(float x){
    unsigned u;
    asm("cvt.rna.tf32.f32 %0, %1;" : "=r"(u) : "f"(x));
    return u;
}

__device__ __forceinline__ void mma8(float* d, const unsigned* a, const unsigned* b){
    asm volatile(
        "mma.sync.aligned.m16n8k8.row.col.f32.tf32.tf32.f32 "
        "{%0,%1,%2,%3}, {%4,%5,%6,%7}, {%8,%9}, {%0,%1,%2,%3};\n"
        : "+f"(d[0]), "+f"(d[1]), "+f"(d[2]), "+f"(d[3])
        : "r"(a[0]), "r"(a[1]), "r"(a[2]), "r"(a[3]), "r"(b[0]), "r"(b[1]));
}

// ---------------- per-node trig tables --------------------------------------
__global__ void trig_kernel(const float* __restrict__ frac){
    int idx = blockIdx.x*blockDim.x + threadIdx.x;
    if (idx >= NN*30) return;
    int n = idx/30; int r = idx - n*30; int dd = r/10; int f = r - dd*10;
    float x = frac[n*3+dd];
    float th = 6.283185307179586f * (float)f * x;
    d_ts[idx] = sinf(th);
    d_tc[idx] = cosf(th);
}

// ---------------- latent: h0 = [emb | t | xrd] @ latent_w + b ---------------
__global__ void __launch_bounds__(256) latent_kernel(
    const float* __restrict__ t, const int* __restrict__ atom_types,
    const int* __restrict__ node2graph, const float* __restrict__ xrd,
    const float* __restrict__ emb, const float* __restrict__ lw,
    const float* __restrict__ lb)
{
    __shared__ float sW[64*Hd];
    __shared__ float sX[48*64];
    int n0 = blockIdx.x*48;
    int tx = threadIdx.x;
    int warp = tx>>5, lane = tx&31, c0 = lane*4;
    float acc[6][4];
    #pragma unroll
    for (int e=0;e<6;e++){
        #pragma unroll
        for (int q=0;q<4;q++) acc[e][q] = lb[c0+q];
    }
    for (int kc=0;kc<6;kc++){
        for (int idx=tx; idx<64*Hd; idx+=256) sW[idx] = lw[kc*64*Hd + idx];
        for (int idx=tx; idx<48*64; idx+=256){
            int nl = idx>>6; int kk = idx&63; int k = kc*64+kk; int n = n0+nl;
            float v;
            if (k < 128)      v = emb[(atom_types[n]-1)*Hd + k];
            else if (k < 256) v = t[node2graph[n]*Hd + (k-128)];
            else              v = xrd[node2graph[n]*Hd + (k-256)];
            sX[idx] = v;
        }
        __syncthreads();
        #pragma unroll 4
        for (int kk=0;kk<64;kk++){
            float4 w4 = *(const float4*)&sW[kk*Hd + c0];
            #pragma unroll
            for (int e=0;e<6;e++){
                float xv = sX[(warp*6+e)*64 + kk];
                acc[e][0] += xv*w4.x; acc[e][1] += xv*w4.y;
                acc[e][2] += xv*w4.z; acc[e][3] += xv*w4.w;
            }
        }
        __syncthreads();
    }
    #pragma unroll
    for (int e=0;e<6;e++){
        float4 o = make_float4(acc[e][0],acc[e][1],acc[e][2],acc[e][3]);
        *(float4*)&d_h[(n0+warp*6+e)*Hd + c0] = o;
    }
}

// ---------------- lattice inner products ------------------------------------
__global__ void latips_kernel(const float* __restrict__ lat){
    int idx = blockIdx.x*blockDim.x + threadIdx.x;
    if (idx >= Gn*9) return;
    int g = idx/9; int rs = idx - g*9; int r = rs/3; int s = rs - r*3;
    const float* Lg = lat + g*9;
    d_latips[idx] = Lg[r*3]*Lg[s*3] + Lg[r*3+1]*Lg[s*3+1] + Lg[r*3+2]*Lg[s*3+2];
}

// ---------------- per-layer lattice projection (+ fold edge_b1) -------------
__global__ void latC_kernel(const float* __restrict__ ew1,
                            const float* __restrict__ eb1, int l){
    int g = blockIdx.x; int c = threadIdx.x;
    float acc = eb1[l*Hd + c];
    const float* wc = ew1 + (l*EINW + 256)*Hd;
    #pragma unroll
    for (int k=0;k<9;k++) acc += d_latips[g*9+k] * wc[k*Hd + c];
    d_latC[g*Hd + c] = acc;
}

// ---------------- per-layer node projections P = h@Wa, Q = h@Wb -------------
__global__ void __launch_bounds__(256) nodeproj_kernel(const float* __restrict__ ew1, int l){
    __shared__ float shT[Hd*24];
    int g = blockIdx.x; int tx = threadIdx.x;
    for (int idx=tx; idx<24*Hd; idx+=256){
        int nl = idx>>7; int k = idx&127;
        shT[k*24+nl] = d_h[(g*24+nl)*Hd + k];
    }
    __syncthreads();
    int c = tx&127; int half = tx>>7;
    const float* W = ew1 + (l*EINW + half*Hd)*Hd;
    float acc[24];
    #pragma unroll
    for (int j=0;j<24;j++) acc[j] = 0.f;
    #pragma unroll 4
    for (int k=0;k<Hd;k++){
        float w = W[k*Hd + c];
        #pragma unroll
        for (int jb=0;jb<6;jb++){
            float4 hv = *(const float4*)&shT[k*24 + jb*4];
            acc[jb*4+0] += hv.x*w; acc[jb*4+1] += hv.y*w;
            acc[jb*4+2] += hv.z*w; acc[jb*4+3] += hv.w*w;
        }
    }
    float* out = half ? d_Q : d_P;
    #pragma unroll
    for (int j=0;j<24;j++) out[(g*24+j)*Hd + c] = acc[j];
}

// ---------------- hot kernel: tf32 tensor-core edge MLP + scatter-mean ------
__global__ void __launch_bounds__(256) edge_kernel(
    const float* __restrict__ ew1, const float* __restrict__ ew2,
    const float* __restrict__ eb2, int l)
{
    extern __shared__ float sm[];
    unsigned* sW2u = (unsigned*)sm;              // [128][136] tf32
    unsigned* sWdu = sW2u + 17408;               // [64][136]  tf32 (rows 60-63 = 0)
    unsigned* sUu  = sWdu + 8704;                // [96][132]  tf32
    unsigned* sFdu = sUu  + 12672;               // [96][68]   tf32 (cols 60-63 = 0)
    float* sP   = (float*)(sFdu + 6528);         // [24][128]
    float* sQ   = sP  + 3072;                    // [24][128]
    float* sS   = sQ  + 3072;                    // [24][30]
    float* sC   = sS  + 720;                     // [24][30]
    float* sLat = sC  + 720;                     // [128]
    float* sB2  = sLat + 128;                    // [128]

    int gr = blockIdx.x;
    int tx = threadIdx.x;
    int warp = tx>>5, lane = tx&31;
    int gq = lane>>2, tg = lane&3;               // mma group id / thread-in-group
    int wx = warp&3, wy = warp>>2;               // warp grid: 2 (M) x 4 (N)
    int n0 = wx*32, m0 = wy*48;

    // ---- stage weights (tf32, padded) ----
    const float* w2 = ew2 + l*Hd*Hd;
    const float* wd = ew1 + (l*EINW + 265)*Hd;
    for (int idx=tx; idx<Hd*Hd; idx+=256){
        int k = idx>>7, c = idx&127;
        sW2u[k*136+c] = tf32_rna(w2[idx]);
    }
    for (int idx=tx; idx<64*Hd; idx+=256){
        int k = idx>>7, c = idx&127;
        sWdu[k*136+c] = (k<60) ? tf32_rna(wd[k*Hd+c]) : 0u;
    }
    for (int idx=tx; idx<24*Hd; idx+=256){
        sP[idx] = d_P[gr*24*Hd + idx];
        sQ[idx] = d_Q[gr*24*Hd + idx];
    }
    for (int idx=tx; idx<720; idx+=256){
        sS[idx] = d_ts[gr*720 + idx];
        sC[idx] = d_tc[gr*720 + idx];
    }
    if (tx < 128){ sLat[tx] = d_latC[gr*Hd+tx]; sB2[tx] = eb2[l*Hd+tx]; }
    __syncthreads();

    for (int it=0; it<6; ++it){
        int i0 = it*4;                            // 4 src nodes per tile
        // ---- build Fd (96 edges x 64) ----
        for (int idx=tx; idx<96*64; idx+=256){
            int e = idx>>6; int k = idx&63;
            unsigned v = 0u;
            if (k < 60){
                int s = e/24; int j = e - s*24; int i = i0+s;
                int df = (k<30) ? k : (k-30);
                float sj = sS[j*30+df], cj = sC[j*30+df];
                float si = sS[i*30+df], ci = sC[i*30+df];
                float x = (k<30) ? (sj*ci - cj*si) : (cj*ci + sj*si);
                v = tf32_rna(x);
            }
            sFdu[e*68+k] = v;
        }
        __syncthreads();

        // ---- GEMM-A: [96x64]@[64x128] ----
        float da[3][4][4];
        #pragma unroll
        for (int mt=0;mt<3;mt++)
            #pragma unroll
            for (int nt=0;nt<4;nt++)
                #pragma unroll
                for (int q=0;q<4;q++) da[mt][nt][q] = 0.f;
        #pragma unroll
        for (int k0=0;k0<64;k0+=8){
            unsigned ua[3][4], ub[4][2];
            #pragma unroll
            for (int mt=0;mt<3;mt++){
                int r = m0 + mt*16 + gq;
                ua[mt][0] = sFdu[r*68 + k0+tg];
                ua[mt][1] = sFdu[(r+8)*68 + k0+tg];
                ua[mt][2] = sFdu[r*68 + k0+tg+4];
                ua[mt][3] = sFdu[(r+8)*68 + k0+tg+4];
            }
            #pragma unroll
            for (int nt=0;nt<4;nt++){
                int c = n0 + nt*8 + gq;
                ub[nt][0] = sWdu[(k0+tg)*136 + c];
                ub[nt][1] = sWdu[(k0+tg+4)*136 + c];
            }
            #pragma unroll
            for (int mt=0;mt<3;mt++)
                #pragma unroll
                for (int nt=0;nt<4;nt++)
                    mma8(da[mt][nt], ua[mt], ub[nt]);
        }
        // ---- epilogue A: + P[src] + Q[dst] + latC, silu, store tf32 U ----
        #pragma unroll
        for (int mt=0;mt<3;mt++){
            #pragma unroll
            for (int nt=0;nt<4;nt++){
                #pragma unroll
                for (int q=0;q<4;q++){
                    int r = m0 + mt*16 + gq + ((q>=2)?8:0);
                    int c = n0 + nt*8 + tg*2 + (q&1);
                    int s = r/24; int j = r - s*24; int i = i0+s;
                    float v = da[mt][nt][q] + sP[i*Hd+c] + sQ[j*Hd+c] + sLat[c];
                    sUu[r*132+c] = tf32_rna(silu_f(v));
                }
            }
        }
        __syncthreads();

        // ---- GEMM-B: [96x128]@[128x128] ----
        float de[3][4][4];
        #pragma unroll
        for (int mt=0;mt<3;mt++)
            #pragma unroll
            for (int nt=0;nt<4;nt++)
                #pragma unroll
                for (int q=0;q<4;q++) de[mt][nt][q] = 0.f;
        #pragma unroll 4
        for (int k0=0;k0<128;k0+=8){
            unsigned ua[3][4], ub[4][2];
            #pragma unroll
            for (int mt=0;mt<3;mt++){
                int r = m0 + mt*16 + gq;
                ua[mt][0] = sUu[r*132 + k0+tg];
                ua[mt][1] = sUu[(r+8)*132 + k0+tg];
                ua[mt][2] = sUu[r*132 + k0+tg+4];
                ua[mt][3] = sUu[(r+8)*132 + k0+tg+4];
            }
            #pragma unroll
            for (int nt=0;nt<4;nt++){
                int c = n0 + nt*8 + gq;
                ub[nt][0] = sW2u[(k0+tg)*136 + c];
                ub[nt][1] = sW2u[(k0+tg+4)*136 + c];
            }
            #pragma unroll
            for (int mt=0;mt<3;mt++)
                #pragma unroll
                for (int nt=0;nt<4;nt++)
                    mma8(de[mt][nt], ua[mt], ub[nt]);
        }
        // ---- epilogue B: +b2, silu, in-register scatter-mean over dst ----
        // warp-row wy owns srcs iA=i0+wy*2, iB=iA+1; rows->src mapping:
        //   mt0(q0..3), mt1(q0,q1) -> src A ; mt1(q2,q3), mt2(q0..3) -> src B
        int iA = i0 + wy*2, iB = iA + 1;
        #pragma unroll
        for (int nt=0;nt<4;nt++){
            #pragma unroll
            for (int qq=0;qq<2;qq++){
                int c = n0 + nt*8 + tg*2 + qq;
                float b = sB2[c];
                float s0 = silu_f(de[0][nt][qq]+b) + silu_f(de[0][nt][2+qq]+b)
                         + silu_f(de[1][nt][qq]+b);
                float s1 = silu_f(de[1][nt][2+qq]+b) + silu_f(de[2][nt][qq]+b)
                         + silu_f(de[2][nt][2+qq]+b);
                #pragma unroll
                for (int off=4;off<32;off<<=1){
                    s0 += __shfl_xor_sync(0xffffffffu, s0, off);
                    s1 += __shfl_xor_sync(0xffffffffu, s1, off);
                }
                if (gq == 0){
                    d_agg[(gr*24 + iA)*Hd + c] = s0 * (1.0f/24.0f);
                    d_agg[(gr*24 + iB)*Hd + c] = s1 * (1.0f/24.0f);
                }
            }
        }
        __syncthreads();
    }
}

// ---------------- per-layer node MLP + residual -----------------------------
__global__ void __launch_bounds__(256) nodemlp_kernel(
    const float* __restrict__ nw1, const float* __restrict__ nb1,
    const float* __restrict__ nw2, const float* __restrict__ nb2, int l)
{
    __shared__ float xT[256*24];
    __shared__ float y1T[Hd*24];
    int g = blockIdx.x; int tx = threadIdx.x;
    for (int idx=tx; idx<24*Hd; idx+=256){
        int nl = idx>>7; int k = idx&127;
        xT[k*24+nl]       = d_h[(g*24+nl)*Hd + k];
        xT[(128+k)*24+nl] = d_agg[(g*24+nl)*Hd + k];
    }
    __syncthreads();
    int c = tx&127; int jh = tx>>7; int jbase = jh*12;
    const float* W1 = nw1 + l*256*Hd;
    float acc[12];
    #pragma unroll
    for (int j=0;j<12;j++) acc[j] = 0.f;
    #pragma unroll 4
    for (int k=0;k<256;k++){
        float w = W1[k*Hd + c];
        #pragma unroll
        for (int jb=0;jb<3;jb++){
            float4 hv = *(const float4*)&xT[k*24 + jbase + jb*4];
            acc[jb*4+0] += hv.x*w; acc[jb*4+1] += hv.y*w;
            acc[jb*4+2] += hv.z*w; acc[jb*4+3] += hv.w*w;
        }
    }
    float b1 = nb1[l*Hd + c];
    #pragma unroll
    for (int j=0;j<12;j++) y1T[c*24 + jbase + j] = silu_f(acc[j] + b1);
    __syncthreads();
    const float* W2 = nw2 + l*Hd*Hd;
    float acc2[12];
    #pragma unroll
    for (int j=0;j<12;j++) acc2[j] = 0.f;
    #pragma unroll 4
    for (int k=0;k<Hd;k++){
        float w = W2[k*Hd + c];
        #pragma unroll
        for (int jb=0;jb<3;jb++){
            float4 yv = *(const float4*)&y1T[k*24 + jbase + jb*4];
            acc2[jb*4+0] += yv.x*w; acc2[jb*4+1] += yv.y*w;
            acc2[jb*4+2] += yv.z*w; acc2[jb*4+3] += yv.w*w;
        }
    }
    float b2v = nb2[l*Hd + c];
    #pragma unroll
    for (int j=0;j<12;j++){
        float o = silu_f(acc2[j] + b2v);
        d_h[(g*24 + jbase + j)*Hd + c] += o;
    }
}

// ---------------- final heads -----------------------------------------------
__global__ void __launch_bounds__(128) final_kernel(
    const float* __restrict__ lat, const float* __restrict__ cw,
    const float* __restrict__ lw, float* __restrict__ out)
{
    __shared__ float sh[24*Hd];
    __shared__ float sgf[Hd];
    __shared__ float smid[9];
    __shared__ float scw[Hd*3];
    int g = blockIdx.x; int tx = threadIdx.x;
    for (int idx=tx; idx<24*Hd; idx+=128) sh[idx] = d_h[g*24*Hd + idx];
    for (int idx=tx; idx<Hd*3; idx+=128) scw[idx] = cw[idx];
    __syncthreads();
    {
        float acc = 0.f;
        #pragma unroll
        for (int a=0;a<24;a++) acc += sh[a*Hd + tx];
        sgf[tx] = acc * (1.0f/24.0f);
    }
    if (tx < 72){
        int n = tx/3; int dd = tx - n*3;
        float s = 0.f;
        #pragma unroll 4
        for (int k=0;k<Hd;k++) s += sh[n*Hd+k]*scw[k*3+dd];
        out[Gn*9 + (g*24+n)*3 + dd] = s;
    }
    __syncthreads();
    if (tx < 9){
        float s = 0.f;
        #pragma unroll 4
        for (int k=0;k<Hd;k++) s += sgf[k]*lw[k*9+tx];
        smid[tx] = s;
    }
    __syncthreads();
    if (tx < 9){
        int r = tx/3; int sc = tx - r*3;
        const float* Lg = lat + g*9;
        out[g*9+tx] = smid[r*3+0]*Lg[0+sc] + smid[r*3+1]*Lg[3+sc]
                    + smid[r*3+2]*Lg[6+sc];
    }
}

// ---------------- launch ----------------------------------------------------
extern "C" void kernel_launch(void* const* d_in, const int* in_sizes, int n_in,
                              void* d_out, int out_size)
{
    const float* t          = (const float*)d_in[0];
    const int*   atom_types = (const int*)  d_in[1];
    const float* frac       = (const float*)d_in[2];
    const float* lattices   = (const float*)d_in[3];
    const int*   node2graph = (const int*)  d_in[5];
    const float* xrd        = (const float*)d_in[6];
    const float* emb        = (const float*)d_in[7];
    const float* latent_w   = (const float*)d_in[8];
    const float* latent_b   = (const float*)d_in[9];
    const float* edge_w1    = (const float*)d_in[10];
    const float* edge_b1    = (const float*)d_in[11];
    const float* edge_w2    = (const float*)d_in[12];
    const float* edge_b2    = (const float*)d_in[13];
    const float* node_w1    = (const float*)d_in[14];
    const float* node_b1    = (const float*)d_in[15];
    const float* node_w2    = (const float*)d_in[16];
    const float* node_b2    = (const float*)d_in[17];
    const float* coord_w    = (const float*)d_in[18];
    const float* lattice_w  = (const float*)d_in[19];
    float* out = (float*)d_out;

    cudaFuncSetAttribute(edge_kernel,
        cudaFuncAttributeMaxDynamicSharedMemorySize, EDGE_SMEM_BYTES);

    trig_kernel<<<(NN*30 + 255)/256, 256>>>(frac);
    latent_kernel<<<NN/48, 256>>>(t, atom_types, node2graph, xrd,
                                  emb, latent_w, latent_b);
    latips_kernel<<<(Gn*9 + 255)/256, 256>>>(lattices);

    for (int l=0; l<NLAYER; ++l){
        latC_kernel<<<Gn, 128>>>(edge_w1, edge_b1, l);
        nodeproj_kernel<<<Gn, 256>>>(edge_w1, l);
        edge_kernel<<<Gn, 256, EDGE_SMEM_BYTES>>>(edge_w1, edge_w2, edge_b2, l);
        nodemlp_kernel<<<Gn, 256>>>(node_w1, node_b1, node_w2, node_b2, l);
    }

    final_kernel<<<Gn, 128>>>(lattices, coord_w, lattice_w, out);
}

// round 3
// speedup vs baseline: 2.3024x; 1.2631x over previous
#include <cuda_runtime.h>
#include <cuda_bf16.h>

#define Gn 512
#define An 24
#define Hd 128
#define NN (Gn*An)
#define NLAYER 4
#define EINW 325

// edge smem: halves: W2 17408 | Wd 8704 | U 13056 | Fd 6912  (=46080 h, 92160B)
// floats: P 3072 | Q 3072 | S 720 | C 720 | Lat 128 | B2 128 (=7840 f, 31360B)
#define EDGE_SMEM_BYTES (92160 + 31360)

// ---------------- scratch -----------------------------------------------------
__device__ float d_h[NN*Hd];
__device__ float d_P[NN*Hd];
__device__ float d_Q[NN*Hd];
__device__ float d_agg[NN*Hd];
__device__ float d_ts[NN*30];
__device__ float d_tc[NN*30];
__device__ float d_latips[Gn*9];

__device__ __forceinline__ float silu_f(float x){
    return __fdividef(x, 1.0f + __expf(-x));
}

__device__ __forceinline__ unsigned pack_bf2(float lo, float hi){
    unsigned r;
    asm("cvt.rn.bf16x2.f32 %0, %1, %2;" : "=r"(r) : "f"(hi), "f"(lo));
    return r;
}

__device__ __forceinline__ void ldsm4(unsigned& r0, unsigned& r1, unsigned& r2,
                                      unsigned& r3, const void* p){
    unsigned a = (unsigned)__cvta_generic_to_shared(p);
    asm volatile("ldmatrix.sync.aligned.m8n8.x4.shared.b16 {%0,%1,%2,%3}, [%4];"
        : "=r"(r0), "=r"(r1), "=r"(r2), "=r"(r3) : "r"(a));
}

__device__ __forceinline__ void ldsm4t(unsigned& r0, unsigned& r1, unsigned& r2,
                                       unsigned& r3, const void* p){
    unsigned a = (unsigned)__cvta_generic_to_shared(p);
    asm volatile("ldmatrix.sync.aligned.m8n8.x4.trans.shared.b16 {%0,%1,%2,%3}, [%4];"
        : "=r"(r0), "=r"(r1), "=r"(r2), "=r"(r3) : "r"(a));
}

__device__ __forceinline__ void mma16(float* d, const unsigned* a, const unsigned* b){
    asm volatile(
        "mma.sync.aligned.m16n8k16.row.col.f32.bf16.bf16.f32 "
        "{%0,%1,%2,%3}, {%4,%5,%6,%7}, {%8,%9}, {%0,%1,%2,%3};\n"
        : "+f"(d[0]), "+f"(d[1]), "+f"(d[2]), "+f"(d[3])
        : "r"(a[0]), "r"(a[1]), "r"(a[2]), "r"(a[3]), "r"(b[0]), "r"(b[1]));
}

// ---------------- per-node trig tables ----------------------------------------
__global__ void trig_kernel(const float* __restrict__ frac){
    int idx = blockIdx.x*blockDim.x + threadIdx.x;
    if (idx >= NN*30) return;
    int n = idx/30; int r = idx - n*30; int dd = r/10; int f = r - dd*10;
    float x = frac[n*3+dd];
    float th = 6.283185307179586f * (float)f * x;
    d_ts[idx] = sinf(th);
    d_tc[idx] = cosf(th);
}

// ---------------- latent ------------------------------------------------------
__global__ void __launch_bounds__(256) latent_kernel(
    const float* __restrict__ t, const int* __restrict__ atom_types,
    const int* __restrict__ node2graph, const float* __restrict__ xrd,
    const float* __restrict__ emb, const float* __restrict__ lw,
    const float* __restrict__ lb)
{
    __shared__ float sW[64*Hd];
    __shared__ float sX[48*64];
    int n0 = blockIdx.x*48;
    int tx = threadIdx.x;
    int warp = tx>>5, lane = tx&31, c0 = lane*4;
    float acc[6][4];
    #pragma unroll
    for (int e=0;e<6;e++){
        #pragma unroll
        for (int q=0;q<4;q++) acc[e][q] = lb[c0+q];
    }
    for (int kc=0;kc<6;kc++){
        for (int idx=tx; idx<64*Hd; idx+=256) sW[idx] = lw[kc*64*Hd + idx];
        for (int idx=tx; idx<48*64; idx+=256){
            int nl = idx>>6; int kk = idx&63; int k = kc*64+kk; int n = n0+nl;
            float v;
            if (k < 128)      v = emb[(atom_types[n]-1)*Hd + k];
            else if (k < 256) v = t[node2graph[n]*Hd + (k-128)];
            else              v = xrd[node2graph[n]*Hd + (k-256)];
            sX[idx] = v;
        }
        __syncthreads();
        #pragma unroll 4
        for (int kk=0;kk<64;kk++){
            float4 w4 = *(const float4*)&sW[kk*Hd + c0];
            #pragma unroll
            for (int e=0;e<6;e++){
                float xv = sX[(warp*6+e)*64 + kk];
                acc[e][0] += xv*w4.x; acc[e][1] += xv*w4.y;
                acc[e][2] += xv*w4.z; acc[e][3] += xv*w4.w;
            }
        }
        __syncthreads();
    }
    #pragma unroll
    for (int e=0;e<6;e++){
        float4 o = make_float4(acc[e][0],acc[e][1],acc[e][2],acc[e][3]);
        *(float4*)&d_h[(n0+warp*6+e)*Hd + c0] = o;
    }
}

// ---------------- lattice inner products --------------------------------------
__global__ void latips_kernel(const float* __restrict__ lat){
    int idx = blockIdx.x*blockDim.x + threadIdx.x;
    if (idx >= Gn*9) return;
    int g = idx/9; int rs = idx - g*9; int r = rs/3; int s = rs - r*3;
    const float* Lg = lat + g*9;
    d_latips[idx] = Lg[r*3]*Lg[s*3] + Lg[r*3+1]*Lg[s*3+1] + Lg[r*3+2]*Lg[s*3+2];
}

// ---------------- per-layer node projections P = h@Wa, Q = h@Wb ---------------
__global__ void __launch_bounds__(256) nodeproj_kernel(const float* __restrict__ ew1, int l){
    __shared__ float shT[Hd*24];
    int g = blockIdx.x; int tx = threadIdx.x;
    for (int idx=tx; idx<24*Hd; idx+=256){
        int nl = idx>>7; int k = idx&127;
        shT[k*24+nl] = d_h[(g*24+nl)*Hd + k];
    }
    __syncthreads();
    int c = tx&127; int half = tx>>7;
    const float* W = ew1 + (l*EINW + half*Hd)*Hd;
    float acc[24];
    #pragma unroll
    for (int j=0;j<24;j++) acc[j] = 0.f;
    #pragma unroll 4
    for (int k=0;k<Hd;k++){
        float w = W[k*Hd + c];
        #pragma unroll
        for (int jb=0;jb<6;jb++){
            float4 hv = *(const float4*)&shT[k*24 + jb*4];
            acc[jb*4+0] += hv.x*w; acc[jb*4+1] += hv.y*w;
            acc[jb*4+2] += hv.z*w; acc[jb*4+3] += hv.w*w;
        }
    }
    float* out = half ? d_Q : d_P;
    #pragma unroll
    for (int j=0;j<24;j++) out[(g*24+j)*Hd + c] = acc[j];
}

// ---------------- hot kernel: bf16 mma + ldmatrix edge MLP --------------------
__global__ void __launch_bounds__(256) edge_kernel(
    const float* __restrict__ ew1, const float* __restrict__ eb1,
    const float* __restrict__ ew2, const float* __restrict__ eb2, int l)
{
    extern __shared__ __align__(16) unsigned char smraw[];
    __nv_bfloat16* sW2h = (__nv_bfloat16*)smraw;     // [128][136] (k-major [k][n])
    __nv_bfloat16* sWdh = sW2h + 17408;              // [64][136]  rows 60-63 = 0
    __nv_bfloat16* sUh  = sWdh + 8704;               // [96][136]
    __nv_bfloat16* sFdh = sUh  + 13056;              // [96][72]   cols 60-71 = 0
    float* sP   = (float*)(sFdh + 6912);             // [24][128]
    float* sQ   = sP  + 3072;
    float* sS   = sQ  + 3072;
    float* sC   = sS  + 720;
    float* sLat = sC  + 720;
    float* sB2  = sLat + 128;

    int gr = blockIdx.x;
    int tx = threadIdx.x;
    int warp = tx>>5, lane = tx&31;
    int gq = lane>>2, tg = lane&3;
    int wx = warp&3, wy = warp>>2;                   // 2(M) x 4(N)
    int n0 = wx*32, m0 = wy*48;
    int row16 = lane & 15;                           // ldmatrix row offset
    int half8 = (lane & 16) ? 8 : 0;                 // ldmatrix col-half offset

    // ---- staging ----
    const float* w2 = ew2 + l*Hd*Hd;
    const float* wd = ew1 + (l*EINW + 265)*Hd;
    for (int idx=tx; idx<Hd*Hd; idx+=256){
        int k = idx>>7, c = idx&127;
        sW2h[k*136+c] = __float2bfloat16_rn(w2[idx]);
    }
    for (int idx=tx; idx<64*Hd; idx+=256){
        int k = idx>>7, c = idx&127;
        sWdh[k*136+c] = (k<60) ? __float2bfloat16_rn(wd[k*Hd+c])
                               : __float2bfloat16_rn(0.f);
    }
    for (int idx=tx; idx<24*Hd; idx+=256){
        sP[idx] = d_P[gr*24*Hd + idx];
        sQ[idx] = d_Q[gr*24*Hd + idx];
    }
    for (int idx=tx; idx<720; idx+=256){
        sS[idx] = d_ts[gr*720 + idx];
        sC[idx] = d_tc[gr*720 + idx];
    }
    if (tx < 128){
        // fused latC: eb1 + latips @ Wc
        float acc = eb1[l*Hd + tx];
        const float* wc = ew1 + (l*EINW + 256)*Hd;
        #pragma unroll
        for (int k=0;k<9;k++) acc += d_latips[gr*9+k] * wc[k*Hd + tx];
        sLat[tx] = acc;
        sB2[tx] = eb2[l*Hd + tx];
    }
    __syncthreads();

    for (int it=0; it<6; ++it){
        int i0 = it*4;                               // 4 src nodes / tile
        // ---- build Fd (96 edges x 72, bf16, cols>=60 zero) ----
        for (int idx=tx; idx<96*72; idx+=256){
            int e = idx/72; int k = idx - e*72;
            float x = 0.f;
            if (k < 60){
                int s = e/24; int j = e - s*24; int i = i0+s;
                int df = (k<30) ? k : (k-30);
                float sj = sS[j*30+df], cj = sC[j*30+df];
                float si = sS[i*30+df], ci = sC[i*30+df];
                x = (k<30) ? (sj*ci - cj*si) : (cj*ci + sj*si);
            }
            sFdh[idx] = __float2bfloat16_rn(x);
        }
        __syncthreads();

        // ---- GEMM-A: Fd[96x64] @ Wd[64x128] ----
        float da[3][4][4];
        #pragma unroll
        for (int mt=0;mt<3;mt++)
            #pragma unroll
            for (int nt=0;nt<4;nt++)
                #pragma unroll
                for (int q=0;q<4;q++) da[mt][nt][q] = 0.f;
        #pragma unroll
        for (int kk=0;kk<4;kk++){
            int k0 = kk*16;
            unsigned ua[3][4], ub[4][2];
            #pragma unroll
            for (int mt=0;mt<3;mt++)
                ldsm4(ua[mt][0],ua[mt][1],ua[mt][2],ua[mt][3],
                      &sFdh[(m0+mt*16+row16)*72 + k0 + half8]);
            #pragma unroll
            for (int np=0;np<2;np++){
                unsigned t0,t1,t2,t3;
                ldsm4t(t0,t1,t2,t3,
                       &sWdh[(k0+row16)*136 + n0+np*16 + half8]);
                ub[2*np][0]=t0; ub[2*np][1]=t1;
                ub[2*np+1][0]=t2; ub[2*np+1][1]=t3;
            }
            #pragma unroll
            for (int mt=0;mt<3;mt++)
                #pragma unroll
                for (int nt=0;nt<4;nt++)
                    mma16(da[mt][nt], ua[mt], ub[nt]);
        }
        // ---- epilogue A: +P[src]+Q[dst]+latC, silu, bf16x2 store to U ----
        #pragma unroll
        for (int mt=0;mt<3;mt++){
            #pragma unroll
            for (int nt=0;nt<4;nt++){
                int c = n0 + nt*8 + tg*2;
                #pragma unroll
                for (int h=0; h<2; h++){
                    int r = m0 + mt*16 + gq + h*8;
                    int s = r/24; int j = r - s*24; int i = i0+s;
                    float base0 = sP[i*Hd+c]   + sQ[j*Hd+c]   + sLat[c];
                    float base1 = sP[i*Hd+c+1] + sQ[j*Hd+c+1] + sLat[c+1];
                    float v0 = silu_f(da[mt][nt][2*h+0] + base0);
                    float v1 = silu_f(da[mt][nt][2*h+1] + base1);
                    *(unsigned*)&sUh[r*136 + c] = pack_bf2(v0, v1);
                }
            }
        }
        __syncthreads();

        // ---- GEMM-B: U[96x128] @ W2[128x128] ----
        float de[3][4][4];
        #pragma unroll
        for (int mt=0;mt<3;mt++)
            #pragma unroll
            for (int nt=0;nt<4;nt++)
                #pragma unroll
                for (int q=0;q<4;q++) de[mt][nt][q] = 0.f;
        #pragma unroll
        for (int kk=0;kk<8;kk++){
            int k0 = kk*16;
            unsigned ua[3][4], ub[4][2];
            #pragma unroll
            for (int mt=0;mt<3;mt++)
                ldsm4(ua[mt][0],ua[mt][1],ua[mt][2],ua[mt][3],
                      &sUh[(m0+mt*16+row16)*136 + k0 + half8]);
            #pragma unroll
            for (int np=0;np<2;np++){
                unsigned t0,t1,t2,t3;
                ldsm4t(t0,t1,t2,t3,
                       &sW2h[(k0+row16)*136 + n0+np*16 + half8]);
                ub[2*np][0]=t0; ub[2*np][1]=t1;
                ub[2*np+1][0]=t2; ub[2*np+1][1]=t3;
            }
            #pragma unroll
            for (int mt=0;mt<3;mt++)
                #pragma unroll
                for (int nt=0;nt<4;nt++)
                    mma16(de[mt][nt], ua[mt], ub[nt]);
        }
        // ---- epilogue B: +b2, silu, in-register scatter-mean over dst ----
        int iA = i0 + wy*2, iB = iA + 1;
        #pragma unroll
        for (int nt=0;nt<4;nt++){
            #pragma unroll
            for (int qq=0;qq<2;qq++){
                int c = n0 + nt*8 + tg*2 + qq;
                float b = sB2[c];
                float s0 = silu_f(de[0][nt][qq]+b) + silu_f(de[0][nt][2+qq]+b)
                         + silu_f(de[1][nt][qq]+b);
                float s1 = silu_f(de[1][nt][2+qq]+b) + silu_f(de[2][nt][qq]+b)
                         + silu_f(de[2][nt][2+qq]+b);
                #pragma unroll
                for (int off=4;off<32;off<<=1){
                    s0 += __shfl_xor_sync(0xffffffffu, s0, off);
                    s1 += __shfl_xor_sync(0xffffffffu, s1, off);
                }
                if (gq == 0){
                    d_agg[(gr*24 + iA)*Hd + c] = s0 * (1.0f/24.0f);
                    d_agg[(gr*24 + iB)*Hd + c] = s1 * (1.0f/24.0f);
                }
            }
        }
        __syncthreads();
    }
}

// ---------------- per-layer node MLP + residual -------------------------------
__global__ void __launch_bounds__(256) nodemlp_kernel(
    const float* __restrict__ nw1, const float* __restrict__ nb1,
    const float* __restrict__ nw2, const float* __restrict__ nb2, int l)
{
    __shared__ float xT[256*24];
    __shared__ float y1T[Hd*24];
    int g = blockIdx.x; int tx = threadIdx.x;
    for (int idx=tx; idx<24*Hd; idx+=256){
        int nl = idx>>7; int k = idx&127;
        xT[k*24+nl]       = d_h[(g*24+nl)*Hd + k];
        xT[(128+k)*24+nl] = d_agg[(g*24+nl)*Hd + k];
    }
    __syncthreads();
    int c = tx&127; int jh = tx>>7; int jbase = jh*12;
    const float* W1 = nw1 + l*256*Hd;
    float acc[12];
    #pragma unroll
    for (int j=0;j<12;j++) acc[j] = 0.f;
    #pragma unroll 4
    for (int k=0;k<256;k++){
        float w = W1[k*Hd + c];
        #pragma unroll
        for (int jb=0;jb<3;jb++){
            float4 hv = *(const float4*)&xT[k*24 + jbase + jb*4];
            acc[jb*4+0] += hv.x*w; acc[jb*4+1] += hv.y*w;
            acc[jb*4+2] += hv.z*w; acc[jb*4+3] += hv.w*w;
        }
    }
    float b1 = nb1[l*Hd + c];
    #pragma unroll
    for (int j=0;j<12;j++) y1T[c*24 + jbase + j] = silu_f(acc[j] + b1);
    __syncthreads();
    const float* W2 = nw2 + l*Hd*Hd;
    float acc2[12];
    #pragma unroll
    for (int j=0;j<12;j++) acc2[j] = 0.f;
    #pragma unroll 4
    for (int k=0;k<Hd;k++){
        float w = W2[k*Hd + c];
        #pragma unroll
        for (int jb=0;jb<3;jb++){
            float4 yv = *(const float4*)&y1T[k*24 + jbase + jb*4];
            acc2[jb*4+0] += yv.x*w; acc2[jb*4+1] += yv.y*w;
            acc2[jb*4+2] += yv.z*w; acc2[jb*4+3] += yv.w*w;
        }
    }
    float b2v = nb2[l*Hd + c];
    #pragma unroll
    for (int j=0;j<12;j++){
        float o = silu_f(acc2[j] + b2v);
        d_h[(g*24 + jbase + j)*Hd + c] += o;
    }
}

// ---------------- final heads -------------------------------------------------
__global__ void __launch_bounds__(128) final_kernel(
    const float* __restrict__ lat, const float* __restrict__ cw,
    const float* __restrict__ lw, float* __restrict__ out)
{
    __shared__ float sh[24*Hd];
    __shared__ float sgf[Hd];
    __shared__ float smid[9];
    __shared__ float scw[Hd*3];
    int g = blockIdx.x; int tx = threadIdx.x;
    for (int idx=tx; idx<24*Hd; idx+=128) sh[idx] = d_h[g*24*Hd + idx];
    for (int idx=tx; idx<Hd*3; idx+=128) scw[idx] = cw[idx];
    __syncthreads();
    {
        float acc = 0.f;
        #pragma unroll
        for (int a=0;a<24;a++) acc += sh[a*Hd + tx];
        sgf[tx] = acc * (1.0f/24.0f);
    }
    if (tx < 72){
        int n = tx/3; int dd = tx - n*3;
        float s = 0.f;
        #pragma unroll 4
        for (int k=0;k<Hd;k++) s += sh[n*Hd+k]*scw[k*3+dd];
        out[Gn*9 + (g*24+n)*3 + dd] = s;
    }
    __syncthreads();
    if (tx < 9){
        float s = 0.f;
        #pragma unroll 4
        for (int k=0;k<Hd;k++) s += sgf[k]*lw[k*9+tx];
        smid[tx] = s;
    }
    __syncthreads();
    if (tx < 9){
        int r = tx/3; int sc = tx - r*3;
        const float* Lg = lat + g*9;
        out[g*9+tx] = smid[r*3+0]*Lg[0+sc] + smid[r*3+1]*Lg[3+sc]
                    + smid[r*3+2]*Lg[6+sc];
    }
}

// ---------------- launch ------------------------------------------------------
extern "C" void kernel_launch(void* const* d_in, const int* in_sizes, int n_in,
                              void* d_out, int out_size)
{
    const float* t          = (const float*)d_in[0];
    const int*   atom_types = (const int*)  d_in[1];
    const float* frac       = (const float*)d_in[2];
    const float* lattices   = (const float*)d_in[3];
    const int*   node2graph = (const int*)  d_in[5];
    const float* xrd        = (const float*)d_in[6];
    const float* emb        = (const float*)d_in[7];
    const float* latent_w   = (const float*)d_in[8];
    const float* latent_b   = (const float*)d_in[9];
    const float* edge_w1    = (const float*)d_in[10];
    const float* edge_b1    = (const float*)d_in[11];
    const float* edge_w2    = (const float*)d_in[12];
    const float* edge_b2    = (const float*)d_in[13];
    const float* node_w1    = (const float*)d_in[14];
    const float* node_b1    = (const float*)d_in[15];
    const float* node_w2    = (const float*)d_in[16];
    const float* node_b2    = (const float*)d_in[17];
    const float* coord_w    = (const float*)d_in[18];
    const float* lattice_w  = (const float*)d_in[19];
    float* out = (float*)d_out;

    cudaFuncSetAttribute(edge_kernel,
        cudaFuncAttributeMaxDynamicSharedMemorySize, EDGE_SMEM_BYTES);

    trig_kernel<<<(NN*30 + 255)/256, 256>>>(frac);
    latent_kernel<<<NN/48, 256>>>(t, atom_types, node2graph, xrd,
                                  emb, latent_w, latent_b);
    latips_kernel<<<(Gn*9 + 255)/256, 256>>>(lattices);

    for (int l=0; l<NLAYER; ++l){
        nodeproj_kernel<<<Gn, 256>>>(edge_w1, l);
        edge_kernel<<<Gn, 256, EDGE_SMEM_BYTES>>>(edge_w1, edge_b1,
                                                  edge_w2, edge_b2, l);
        nodemlp_kernel<<<Gn, 256>>>(node_w1, node_b1, node_w2, node_b2, l);
    }

    final_kernel<<<Gn, 128>>>(lattices, coord_w, lattice_w, out);
}

// round 5
// speedup vs baseline: 2.6415x; 1.1472x over previous
#include <cuda_runtime.h>
#include <cuda_bf16.h>

#define Gn 512
#define An 24
#define Hd 128
#define NN (Gn*An)
#define NLAYER 4
#define EINW 325

#define EDGE_SMEM_BYTES (92160 + 31360)
// nodeproj (tf32): sH [96][132] + sW [128][264] u32
#define NP_SMEM_BYTES ((96*132 + 128*264)*4)
// nodemlp (tf32): sX [96][260] + sWb [128][136] + sY [96][132] u32 + 256 f32 bias
#define NM_SMEM_BYTES ((96*260 + 128*136 + 96*132)*4 + 1024)

// ---------------- scratch -----------------------------------------------------
__device__ float d_h[NN*Hd];
__device__ float d_P[NN*Hd];
__device__ float d_Q[NN*Hd];
__device__ float d_agg[NN*Hd];
__device__ float d_ts[NN*30];
__device__ float d_tc[NN*30];
__device__ float d_latips[Gn*9];

__device__ __forceinline__ float silu_f(float x){
    return __fdividef(x, 1.0f + __expf(-x));
}

__device__ __forceinline__ unsigned pack_bf2(float lo, float hi){
    unsigned r;
    asm("cvt.rn.bf16x2.f32 %0, %1, %2;" : "=r"(r) : "f"(hi), "f"(lo));
    return r;
}

__device__ __forceinline__ unsigned tf32_rna(float x){
    unsigned u;
    asm("cvt.rna.tf32.f32 %0, %1;" : "=r"(u) : "f"(x));
    return u;
}

__device__ __forceinline__ void ldsm4(unsigned& r0, unsigned& r1, unsigned& r2,
                                      unsigned& r3, const void* p){
    unsigned a = (unsigned)__cvta_generic_to_shared(p);
    asm volatile("ldmatrix.sync.aligned.m8n8.x4.shared.b16 {%0,%1,%2,%3}, [%4];"
        : "=r"(r0), "=r"(r1), "=r"(r2), "=r"(r3) : "r"(a));
}

__device__ __forceinline__ void ldsm4t(unsigned& r0, unsigned& r1, unsigned& r2,
                                       unsigned& r3, const void* p){
    unsigned a = (unsigned)__cvta_generic_to_shared(p);
    asm volatile("ldmatrix.sync.aligned.m8n8.x4.trans.shared.b16 {%0,%1,%2,%3}, [%4];"
        : "=r"(r0), "=r"(r1), "=r"(r2), "=r"(r3) : "r"(a));
}

__device__ __forceinline__ void mma16(float* d, const unsigned* a, const unsigned* b){
    asm volatile(
        "mma.sync.aligned.m16n8k16.row.col.f32.bf16.bf16.f32 "
        "{%0,%1,%2,%3}, {%4,%5,%6,%7}, {%8,%9}, {%0,%1,%2,%3};\n"
        : "+f"(d[0]), "+f"(d[1]), "+f"(d[2]), "+f"(d[3])
        : "r"(a[0]), "r"(a[1]), "r"(a[2]), "r"(a[3]), "r"(b[0]), "r"(b[1]));
}

__device__ __forceinline__ void mma8(float* d, const unsigned* a, const unsigned* b){
    asm volatile(
        "mma.sync.aligned.m16n8k8.row.col.f32.tf32.tf32.f32 "
        "{%0,%1,%2,%3}, {%4,%5,%6,%7}, {%8,%9}, {%0,%1,%2,%3};\n"
        : "+f"(d[0]), "+f"(d[1]), "+f"(d[2]), "+f"(d[3])
        : "r"(a[0]), "r"(a[1]), "r"(a[2]), "r"(a[3]), "r"(b[0]), "r"(b[1]));
}

// ---------------- per-node trig tables ----------------------------------------
__global__ void trig_kernel(const float* __restrict__ frac){
    int idx = blockIdx.x*blockDim.x + threadIdx.x;
    if (idx >= NN*30) return;
    int n = idx/30; int r = idx - n*30; int dd = r/10; int f = r - dd*10;
    float x = frac[n*3+dd];
    float th = 6.283185307179586f * (float)f * x;
    d_ts[idx] = sinf(th);
    d_tc[idx] = cosf(th);
}

// ---------------- latent ------------------------------------------------------
__global__ void __launch_bounds__(256) latent_kernel(
    const float* __restrict__ t, const int* __restrict__ atom_types,
    const int* __restrict__ node2graph, const float* __restrict__ xrd,
    const float* __restrict__ emb, const float* __restrict__ lw,
    const float* __restrict__ lb)
{
    __shared__ float sW[64*Hd];
    __shared__ float sX[48*64];
    int n0 = blockIdx.x*48;
    int tx = threadIdx.x;
    int warp = tx>>5, lane = tx&31, c0 = lane*4;
    float acc[6][4];
    #pragma unroll
    for (int e=0;e<6;e++){
        #pragma unroll
        for (int q=0;q<4;q++) acc[e][q] = lb[c0+q];
    }
    for (int kc=0;kc<6;kc++){
        for (int idx=tx; idx<64*Hd; idx+=256) sW[idx] = lw[kc*64*Hd + idx];
        for (int idx=tx; idx<48*64; idx+=256){
            int nl = idx>>6; int kk = idx&63; int k = kc*64+kk; int n = n0+nl;
            float v;
            if (k < 128)      v = emb[(atom_types[n]-1)*Hd + k];
            else if (k < 256) v = t[node2graph[n]*Hd + (k-128)];
            else              v = xrd[node2graph[n]*Hd + (k-256)];
            sX[idx] = v;
        }
        __syncthreads();
        #pragma unroll 4
        for (int kk=0;kk<64;kk++){
            float4 w4 = *(const float4*)&sW[kk*Hd + c0];
            #pragma unroll
            for (int e=0;e<6;e++){
                float xv = sX[(warp*6+e)*64 + kk];
                acc[e][0] += xv*w4.x; acc[e][1] += xv*w4.y;
                acc[e][2] += xv*w4.z; acc[e][3] += xv*w4.w;
            }
        }
        __syncthreads();
    }
    #pragma unroll
    for (int e=0;e<6;e++){
        float4 o = make_float4(acc[e][0],acc[e][1],acc[e][2],acc[e][3]);
        *(float4*)&d_h[(n0+warp*6+e)*Hd + c0] = o;
    }
}

// ---------------- lattice inner products --------------------------------------
__global__ void latips_kernel(const float* __restrict__ lat){
    int idx = blockIdx.x*blockDim.x + threadIdx.x;
    if (idx >= Gn*9) return;
    int g = idx/9; int rs = idx - g*9; int r = rs/3; int s = rs - r*3;
    const float* Lg = lat + g*9;
    d_latips[idx] = Lg[r*3]*Lg[s*3] + Lg[r*3+1]*Lg[s*3+1] + Lg[r*3+2]*Lg[s*3+2];
}

// ---------------- nodeproj (tf32 tensor core, 4 graphs/CTA) -------------------
// P|Q [96x256] = h[96x128] @ Wab[128x256]
__global__ void __launch_bounds__(256) nodeproj_tc(const float* __restrict__ ew1, int l){
    extern __shared__ __align__(16) unsigned smu[];
    unsigned* sH = smu;              // [96][132]  (132 mod 32 = 4)
    unsigned* sW = sH + 96*132;      // [128][264] (264 mod 32 = 8)
    int g0 = blockIdx.x*4;
    int tx = threadIdx.x;
    int warp = tx>>5, lane = tx&31;
    int gq = lane>>2, tg = lane&3;
    int wx = warp&3, wy = warp>>2;
    int m0 = wy*48, nbase = wx*64;

    for (int idx=tx; idx<96*Hd; idx+=256){
        int r = idx>>7, c = idx&127;
        sH[r*132+c] = tf32_rna(d_h[g0*24*Hd + idx]);
    }
    for (int idx=tx; idx<128*256; idx+=256){
        int k = idx>>8, n = idx&255;
        float v = (n<128) ? ew1[(l*EINW + k)*Hd + n]
                          : ew1[(l*EINW + 128 + k)*Hd + (n-128)];
        sW[k*264+n] = tf32_rna(v);
    }
    __syncthreads();

    float acc[3][8][4];
    #pragma unroll
    for (int mt=0;mt<3;mt++)
        #pragma unroll
        for (int nt=0;nt<8;nt++)
            #pragma unroll
            for (int q=0;q<4;q++) acc[mt][nt][q] = 0.f;

    #pragma unroll 4
    for (int kk=0;kk<16;kk++){
        int k0 = kk*8;
        unsigned ua[3][4], ub[8][2];
        #pragma unroll
        for (int mt=0;mt<3;mt++){
            int r = m0 + mt*16 + gq;
            ua[mt][0] = sH[r*132 + k0+tg];
            ua[mt][1] = sH[(r+8)*132 + k0+tg];
            ua[mt][2] = sH[r*132 + k0+tg+4];
            ua[mt][3] = sH[(r+8)*132 + k0+tg+4];
        }
        #pragma unroll
        for (int nt=0;nt<8;nt++){
            int c = nbase + nt*8 + gq;
            ub[nt][0] = sW[(k0+tg)*264 + c];
            ub[nt][1] = sW[(k0+tg+4)*264 + c];
        }
        #pragma unroll
        for (int mt=0;mt<3;mt++)
            #pragma unroll
            for (int nt=0;nt<8;nt++)
                mma8(acc[mt][nt], ua[mt], ub[nt]);
    }

    #pragma unroll
    for (int mt=0;mt<3;mt++){
        #pragma unroll
        for (int nt=0;nt<8;nt++){
            int c = nbase + nt*8 + tg*2;
            #pragma unroll
            for (int h=0;h<2;h++){
                int r = m0 + mt*16 + gq + h*8;
                float2 v = make_float2(acc[mt][nt][2*h+0], acc[mt][nt][2*h+1]);
                if (c < 128) *(float2*)&d_P[(g0*24+r)*Hd + c] = v;
                else         *(float2*)&d_Q[(g0*24+r)*Hd + (c-128)] = v;
            }
        }
    }
}

// ---------------- hot kernel: bf16 mma + ldmatrix edge MLP --------------------
__global__ void __launch_bounds__(256) edge_kernel(
    const float* __restrict__ ew1, const float* __restrict__ eb1,
    const float* __restrict__ ew2, const float* __restrict__ eb2, int l)
{
    extern __shared__ __align__(16) unsigned char smraw[];
    __nv_bfloat16* sW2h = (__nv_bfloat16*)smraw;     // [128][136]
    __nv_bfloat16* sWdh = sW2h + 17408;              // [64][136] rows>=60 zero
    __nv_bfloat16* sUh  = sWdh + 8704;               // [96][136]
    __nv_bfloat16* sFdh = sUh  + 13056;              // [96][72]  cols>=60 zero
    float* sP   = (float*)(sFdh + 6912);
    float* sQ   = sP  + 3072;
    float* sS   = sQ  + 3072;
    float* sC   = sS  + 720;
    float* sLat = sC  + 720;
    float* sB2  = sLat + 128;

    int gr = blockIdx.x;
    int tx = threadIdx.x;
    int warp = tx>>5, lane = tx&31;
    int gq = lane>>2, tg = lane&3;
    int wx = warp&3, wy = warp>>2;
    int n0 = wx*32, m0 = wy*48;
    int row16 = lane & 15;
    int half8 = (lane & 16) ? 8 : 0;

    const float* w2 = ew2 + l*Hd*Hd;
    const float* wd = ew1 + (l*EINW + 265)*Hd;
    for (int idx=tx; idx<Hd*Hd; idx+=256){
        int k = idx>>7, c = idx&127;
        sW2h[k*136+c] = __float2bfloat16_rn(w2[idx]);
    }
    for (int idx=tx; idx<64*Hd; idx+=256){
        int k = idx>>7, c = idx&127;
        sWdh[k*136+c] = (k<60) ? __float2bfloat16_rn(wd[k*Hd+c])
                               : __float2bfloat16_rn(0.f);
    }
    for (int idx=tx; idx<24*Hd; idx+=256){
        sP[idx] = d_P[gr*24*Hd + idx];
        sQ[idx] = d_Q[gr*24*Hd + idx];
    }
    for (int idx=tx; idx<720; idx+=256){
        sS[idx] = d_ts[gr*720 + idx];
        sC[idx] = d_tc[gr*720 + idx];
    }
    if (tx < 128){
        float acc = eb1[l*Hd + tx];
        const float* wc = ew1 + (l*EINW + 256)*Hd;
        #pragma unroll
        for (int k=0;k<9;k++) acc += d_latips[gr*9+k] * wc[k*Hd + tx];
        sLat[tx] = acc;
        sB2[tx] = eb2[l*Hd + tx];
    }
    __syncthreads();

    for (int it=0; it<6; ++it){
        int i0 = it*4;
        for (int idx=tx; idx<96*72; idx+=256){
            int e = idx/72; int k = idx - e*72;
            float x = 0.f;
            if (k < 60){
                int s = e/24; int j = e - s*24; int i = i0+s;
                int df = (k<30) ? k : (k-30);
                float sj = sS[j*30+df], cj = sC[j*30+df];
                float si = sS[i*30+df], ci = sC[i*30+df];
                x = (k<30) ? (sj*ci - cj*si) : (cj*ci + sj*si);
            }
            sFdh[idx] = __float2bfloat16_rn(x);
        }
        __syncthreads();

        float da[3][4][4];
        #pragma unroll
        for (int mt=0;mt<3;mt++)
            #pragma unroll
            for (int nt=0;nt<4;nt++)
                #pragma unroll
                for (int q=0;q<4;q++) da[mt][nt][q] = 0.f;
        #pragma unroll
        for (int kk=0;kk<4;kk++){
            int k0 = kk*16;
            unsigned ua[3][4], ub[4][2];
            #pragma unroll
            for (int mt=0;mt<3;mt++)
                ldsm4(ua[mt][0],ua[mt][1],ua[mt][2],ua[mt][3],
                      &sFdh[(m0+mt*16+row16)*72 + k0 + half8]);
            #pragma unroll
            for (int np=0;np<2;np++){
                unsigned t0,t1,t2,t3;
                ldsm4t(t0,t1,t2,t3, &sWdh[(k0+row16)*136 + n0+np*16 + half8]);
                ub[2*np][0]=t0; ub[2*np][1]=t1;
                ub[2*np+1][0]=t2; ub[2*np+1][1]=t3;
            }
            #pragma unroll
            for (int mt=0;mt<3;mt++)
                #pragma unroll
                for (int nt=0;nt<4;nt++)
                    mma16(da[mt][nt], ua[mt], ub[nt]);
        }
        #pragma unroll
        for (int mt=0;mt<3;mt++){
            #pragma unroll
            for (int nt=0;nt<4;nt++){
                int c = n0 + nt*8 + tg*2;
                #pragma unroll
                for (int h=0; h<2; h++){
                    int r = m0 + mt*16 + gq + h*8;
                    int s = r/24; int j = r - s*24; int i = i0+s;
                    float base0 = sP[i*Hd+c]   + sQ[j*Hd+c]   + sLat[c];
                    float base1 = sP[i*Hd+c+1] + sQ[j*Hd+c+1] + sLat[c+1];
                    float v0 = silu_f(da[mt][nt][2*h+0] + base0);
                    float v1 = silu_f(da[mt][nt][2*h+1] + base1);
                    *(unsigned*)&sUh[r*136 + c] = pack_bf2(v0, v1);
                }
            }
        }
        __syncthreads();

        float de[3][4][4];
        #pragma unroll
        for (int mt=0;mt<3;mt++)
            #pragma unroll
            for (int nt=0;nt<4;nt++)
                #pragma unroll
                for (int q=0;q<4;q++) de[mt][nt][q] = 0.f;
        #pragma unroll
        for (int kk=0;kk<8;kk++){
            int k0 = kk*16;
            unsigned ua[3][4], ub[4][2];
            #pragma unroll
            for (int mt=0;mt<3;mt++)
                ldsm4(ua[mt][0],ua[mt][1],ua[mt][2],ua[mt][3],
                      &sUh[(m0+mt*16+row16)*136 + k0 + half8]);
            #pragma unroll
            for (int np=0;np<2;np++){
                unsigned t0,t1,t2,t3;
                ldsm4t(t0,t1,t2,t3, &sW2h[(k0+row16)*136 + n0+np*16 + half8]);
                ub[2*np][0]=t0; ub[2*np][1]=t1;
                ub[2*np+1][0]=t2; ub[2*np+1][1]=t3;
            }
            #pragma unroll
            for (int mt=0;mt<3;mt++)
                #pragma unroll
                for (int nt=0;nt<4;nt++)
                    mma16(de[mt][nt], ua[mt], ub[nt]);
        }
        int iA = i0 + wy*2, iB = iA + 1;
        #pragma unroll
        for (int nt=0;nt<4;nt++){
            #pragma unroll
            for (int qq=0;qq<2;qq++){
                int c = n0 + nt*8 + tg*2 + qq;
                float b = sB2[c];
                float s0 = silu_f(de[0][nt][qq]+b) + silu_f(de[0][nt][2+qq]+b)
                         + silu_f(de[1][nt][qq]+b);
                float s1 = silu_f(de[1][nt][2+qq]+b) + silu_f(de[2][nt][qq]+b)
                         + silu_f(de[2][nt][2+qq]+b);
                #pragma unroll
                for (int off=4;off<32;off<<=1){
                    s0 += __shfl_xor_sync(0xffffffffu, s0, off);
                    s1 += __shfl_xor_sync(0xffffffffu, s1, off);
                }
                if (gq == 0){
                    d_agg[(gr*24 + iA)*Hd + c] = s0 * (1.0f/24.0f);
                    d_agg[(gr*24 + iB)*Hd + c] = s1 * (1.0f/24.0f);
                }
            }
        }
        __syncthreads();
    }
}

// ---------------- node MLP (tf32 tensor core, 4 graphs/CTA) -------------------
__global__ void __launch_bounds__(256) nodemlp_tc(
    const float* __restrict__ nw1, const float* __restrict__ nb1,
    const float* __restrict__ nw2, const float* __restrict__ nb2, int l)
{
    extern __shared__ __align__(16) unsigned smu[];
    unsigned* sX  = smu;               // [96][260] (260 mod 32 = 4)
    unsigned* sWb = sX + 96*260;       // [128][136] W1 chunks, then W2
    unsigned* sY  = sWb + 128*136;     // [96][132]
    float* sB = (float*)(sY + 96*132); // b1[128] | b2[128]

    int g0 = blockIdx.x*4;
    int tx = threadIdx.x;
    int warp = tx>>5, lane = tx&31;
    int gq = lane>>2, tg = lane&3;
    int wx = warp&3, wy = warp>>2;
    int m0 = wy*48, n0 = wx*32;

    for (int idx=tx; idx<96*256; idx+=256){
        int r = idx>>8, k = idx&255;
        float v = (k<128) ? d_h[(g0*24+r)*Hd + k]
                          : d_agg[(g0*24+r)*Hd + (k-128)];
        sX[r*260+k] = tf32_rna(v);
    }
    if (tx < 128){ sB[tx] = nb1[l*Hd+tx]; sB[128+tx] = nb2[l*Hd+tx]; }

    const float* W1 = nw1 + l*256*Hd;
    float a1[3][4][4];
    #pragma unroll
    for (int mt=0;mt<3;mt++)
        #pragma unroll
        for (int nt=0;nt<4;nt++)
            #pragma unroll
            for (int q=0;q<4;q++) a1[mt][nt][q] = 0.f;

    for (int kc=0; kc<2; kc++){
        for (int idx=tx; idx<128*Hd; idx+=256){
            int k = idx>>7, c = idx&127;
            sWb[k*136+c] = tf32_rna(W1[(kc*128+k)*Hd + c]);
        }
        __syncthreads();
        #pragma unroll 4
        for (int kk=0;kk<16;kk++){
            int ka = kc*128 + kk*8;   // global k for X
            int kb = kk*8;            // local k for W chunk
            unsigned ua[3][4], ub[4][2];
            #pragma unroll
            for (int mt=0;mt<3;mt++){
                int r = m0 + mt*16 + gq;
                ua[mt][0] = sX[r*260 + ka+tg];
                ua[mt][1] = sX[(r+8)*260 + ka+tg];
                ua[mt][2] = sX[r*260 + ka+tg+4];
                ua[mt][3] = sX[(r+8)*260 + ka+tg+4];
            }
            #pragma unroll
            for (int nt=0;nt<4;nt++){
                int c = n0 + nt*8 + gq;
                ub[nt][0] = sWb[(kb+tg)*136 + c];
                ub[nt][1] = sWb[(kb+tg+4)*136 + c];
            }
            #pragma unroll
            for (int mt=0;mt<3;mt++)
                #pragma unroll
                for (int nt=0;nt<4;nt++)
                    mma8(a1[mt][nt], ua[mt], ub[nt]);
        }
        __syncthreads();
    }

    // epilogue 1: silu -> tf32 Y ; stage W2 into sWb (now free)
    #pragma unroll
    for (int mt=0;mt<3;mt++){
        #pragma unroll
        for (int nt=0;nt<4;nt++){
            int c = n0 + nt*8 + tg*2;
            #pragma unroll
            for (int h=0;h<2;h++){
                int r = m0 + mt*16 + gq + h*8;
                sY[r*132 + c]   = tf32_rna(silu_f(a1[mt][nt][2*h+0] + sB[c]));
                sY[r*132 + c+1] = tf32_rna(silu_f(a1[mt][nt][2*h+1] + sB[c+1]));
            }
        }
    }
    const float* W2 = nw2 + l*Hd*Hd;
    for (int idx=tx; idx<Hd*Hd; idx+=256){
        int k = idx>>7, c = idx&127;
        sWb[k*136+c] = tf32_rna(W2[idx]);
    }
    __syncthreads();

    // GEMM2: [96x128] @ [128x128]
    float a2[3][4][4];
    #pragma unroll
    for (int mt=0;mt<3;mt++)
        #pragma unroll
        for (int nt=0;nt<4;nt++)
            #pragma unroll
            for (int q=0;q<4;q++) a2[mt][nt][q] = 0.f;
    #pragma unroll 4
    for (int kk=0;kk<16;kk++){
        int k0 = kk*8;
        unsigned ua[3][4], ub[4][2];
        #pragma unroll
        for (int mt=0;mt<3;mt++){
            int r = m0 + mt*16 + gq;
            ua[mt][0] = sY[r*132 + k0+tg];
            ua[mt][1] = sY[(r+8)*132 + k0+tg];
            ua[mt][2] = sY[r*132 + k0+tg+4];
            ua[mt][3] = sY[(r+8)*132 + k0+tg+4];
        }
        #pragma unroll
        for (int nt=0;nt<4;nt++){
            int c = n0 + nt*8 + gq;
            ub[nt][0] = sWb[(k0+tg)*136 + c];
            ub[nt][1] = sWb[(k0+tg+4)*136 + c];
        }
        #pragma unroll
        for (int mt=0;mt<3;mt++)
            #pragma unroll
            for (int nt=0;nt<4;nt++)
                mma8(a2[mt][nt], ua[mt], ub[nt]);
    }
    #pragma unroll
    for (int mt=0;mt<3;mt++){
        #pragma unroll
        for (int nt=0;nt<4;nt++){
            int c = n0 + nt*8 + tg*2;
            #pragma unroll
            for (int h=0;h<2;h++){
                int r = m0 + mt*16 + gq + h*8;
                float o0 = silu_f(a2[mt][nt][2*h+0] + sB[128+c]);
                float o1 = silu_f(a2[mt][nt][2*h+1] + sB[128+c+1]);
                float2* p = (float2*)&d_h[(g0*24+r)*Hd + c];
                float2 old = *p;
                old.x += o0; old.y += o1;
                *p = old;
            }
        }
    }
}

// ---------------- final heads -------------------------------------------------
__global__ void __launch_bounds__(128) final_kernel(
    const float* __restrict__ lat, const float* __restrict__ cw,
    const float* __restrict__ lw, float* __restrict__ out)
{
    __shared__ float sh[24*Hd];
    __shared__ float sgf[Hd];
    __shared__ float smid[9];
    __shared__ float scw[Hd*3];
    int g = blockIdx.x; int tx = threadIdx.x;
    for (int idx=tx; idx<24*Hd; idx+=128) sh[idx] = d_h[g*24*Hd + idx];
    for (int idx=tx; idx<Hd*3; idx+=128) scw[idx] = cw[idx];
    __syncthreads();
    {
        float acc = 0.f;
        #pragma unroll
        for (int a=0;a<24;a++) acc += sh[a*Hd + tx];
        sgf[tx] = acc * (1.0f/24.0f);
    }
    if (tx < 72){
        int n = tx/3; int dd = tx - n*3;
        float s = 0.f;
        #pragma unroll 4
        for (int k=0;k<Hd;k++) s += sh[n*Hd+k]*scw[k*3+dd];
        out[Gn*9 + (g*24+n)*3 + dd] = s;
    }
    __syncthreads();
    if (tx < 9){
        float s = 0.f;
        #pragma unroll 4
        for (int k=0;k<Hd;k++) s += sgf[k]*lw[k*9+tx];
        smid[tx] = s;
    }
    __syncthreads();
    if (tx < 9){
        int r = tx/3; int sc = tx - r*3;
        const float* Lg = lat + g*9;
        out[g*9+tx] = smid[r*3+0]*Lg[0+sc] + smid[r*3+1]*Lg[3+sc]
                    + smid[r*3+2]*Lg[6+sc];
    }
}

// ---------------- launch ------------------------------------------------------
extern "C" void kernel_launch(void* const* d_in, const int* in_sizes, int n_in,
                              void* d_out, int out_size)
{
    const float* t          = (const float*)d_in[0];
    const int*   atom_types = (const int*)  d_in[1];
    const float* frac       = (const float*)d_in[2];
    const float* lattices   = (const float*)d_in[3];
    const int*   node2graph = (const int*)  d_in[5];
    const float* xrd        = (const float*)d_in[6];
    const float* emb        = (const float*)d_in[7];
    const float* latent_w   = (const float*)d_in[8];
    const float* latent_b   = (const float*)d_in[9];
    const float* edge_w1    = (const float*)d_in[10];
    const float* edge_b1    = (const float*)d_in[11];
    const float* edge_w2    = (const float*)d_in[12];
    const float* edge_b2    = (const float*)d_in[13];
    const float* node_w1    = (const float*)d_in[14];
    const float* node_b1    = (const float*)d_in[15];
    const float* node_w2    = (const float*)d_in[16];
    const float* node_b2    = (const float*)d_in[17];
    const float* coord_w    = (const float*)d_in[18];
    const float* lattice_w  = (const float*)d_in[19];
    float* out = (float*)d_out;

    cudaFuncSetAttribute(edge_kernel,
        cudaFuncAttributeMaxDynamicSharedMemorySize, EDGE_SMEM_BYTES);
    cudaFuncSetAttribute(nodeproj_tc,
        cudaFuncAttributeMaxDynamicSharedMemorySize, NP_SMEM_BYTES);
    cudaFuncSetAttribute(nodemlp_tc,
        cudaFuncAttributeMaxDynamicSharedMemorySize, NM_SMEM_BYTES);

    trig_kernel<<<(NN*30 + 255)/256, 256>>>(frac);
    latent_kernel<<<NN/48, 256>>>(t, atom_types, node2graph, xrd,
                                  emb, latent_w, latent_b);
    latips_kernel<<<(Gn*9 + 255)/256, 256>>>(lattices);

    for (int l=0; l<NLAYER; ++l){
        nodeproj_tc<<<Gn/4, 256, NP_SMEM_BYTES>>>(edge_w1, l);
        edge_kernel<<<Gn, 256, EDGE_SMEM_BYTES>>>(edge_w1, edge_b1,
                                                  edge_w2, edge_b2, l);
        nodemlp_tc<<<Gn/4, 256, NM_SMEM_BYTES>>>(node_w1, node_b1,
                                                 node_w2, node_b2, l);
    }

    final_kernel<<<Gn, 128>>>(lattices, coord_w, lattice_w, out);
}

// round 8
// speedup vs baseline: 3.6408x; 1.3783x over previous
#include <cuda_runtime.h>
#include <cuda_bf16.h>

#define Gn 512
#define An 24
#define Hd 128
#define NN (Gn*An)
#define NLAYER 4
#define EINW 325

// edge: halves W2 17408 | Wd 8704 | U(alias Fd) 13056 ; floats P,Q,S,C,Lat,B2
#define EDGE_SMEM_BYTES ((17408+8704+13056)*2 + (3072+3072+720+720+128+128)*4)
// nodeproj (tf32): sH [96][132] + sW [128][264] u32
#define NP_SMEM_BYTES ((96*132 + 128*264)*4)
// node_fused: sX [96][260] | sWb [128][136] | sY [96][132] u32 | 256 f32 bias
#define NF_SMEM_BYTES ((96*260 + 128*136 + 96*132 + 256)*4)

// ---------------- scratch -----------------------------------------------------
__device__ float d_h[NN*Hd];
__device__ float d_P[NN*Hd];
__device__ float d_Q[NN*Hd];
__device__ float d_agg[NN*Hd];
__device__ float d_ts[NN*30];
__device__ float d_tc[NN*30];
__device__ float d_latips[Gn*9];
__device__ __align__(16) __nv_bfloat16 d_W2bf[NLAYER*128*136];
__device__ __align__(16) __nv_bfloat16 d_Wdbf[NLAYER*64*136];

__device__ __forceinline__ float silu_f(float x){
    return __fdividef(x, 1.0f + __expf(-x));
}

__device__ __forceinline__ unsigned pack_bf2(float lo, float hi){
    unsigned r;
    asm("cvt.rn.bf16x2.f32 %0, %1, %2;" : "=r"(r) : "f"(hi), "f"(lo));
    return r;
}

__device__ __forceinline__ unsigned tf32_rna(float x){
    unsigned u;
    asm("cvt.rna.tf32.f32 %0, %1;" : "=r"(u) : "f"(x));
    return u;
}

__device__ __forceinline__ void ldsm4(unsigned& r0, unsigned& r1, unsigned& r2,
                                      unsigned& r3, const void* p){
    unsigned a = (unsigned)__cvta_generic_to_shared(p);
    asm volatile("ldmatrix.sync.aligned.m8n8.x4.shared.b16 {%0,%1,%2,%3}, [%4];"
        : "=r"(r0), "=r"(r1), "=r"(r2), "=r"(r3) : "r"(a));
}

__device__ __forceinline__ void ldsm4t(unsigned& r0, unsigned& r1, unsigned& r2,
                                       unsigned& r3, const void* p){
    unsigned a = (unsigned)__cvta_generic_to_shared(p);
    asm volatile("ldmatrix.sync.aligned.m8n8.x4.trans.shared.b16 {%0,%1,%2,%3}, [%4];"
        : "=r"(r0), "=r"(r1), "=r"(r2), "=r"(r3) : "r"(a));
}

__device__ __forceinline__ void mma16(float* d, const unsigned* a, const unsigned* b){
    asm volatile(
        "mma.sync.aligned.m16n8k16.row.col.f32.bf16.bf16.f32 "
        "{%0,%1,%2,%3}, {%4,%5,%6,%7}, {%8,%9}, {%0,%1,%2,%3};\n"
        : "+f"(d[0]), "+f"(d[1]), "+f"(d[2]), "+f"(d[3])
        : "r"(a[0]), "r"(a[1]), "r"(a[2]), "r"(a[3]), "r"(b[0]), "r"(b[1]));
}

__device__ __forceinline__ void mma8(float* d, const unsigned* a, const unsigned* b){
    asm volatile(
        "mma.sync.aligned.m16n8k8.row.col.f32.tf32.tf32.f32 "
        "{%0,%1,%2,%3}, {%4,%5,%6,%7}, {%8,%9}, {%0,%1,%2,%3};\n"
        : "+f"(d[0]), "+f"(d[1]), "+f"(d[2]), "+f"(d[3])
        : "r"(a[0]), "r"(a[1]), "r"(a[2]), "r"(a[3]), "r"(b[0]), "r"(b[1]));
}

// ---------------- weight pre-conversion (bf16, padded) -------------------------
__global__ void wconv_kernel(const float* __restrict__ ew1,
                             const float* __restrict__ ew2){
    int idx = blockIdx.x*256 + threadIdx.x;
    if (idx < NLAYER*128*136){
        int l = idx/(128*136); int r = idx - l*128*136;
        int k = r/136, c = r - k*136;
        float v = (c<128) ? ew2[(l*128 + k)*Hd + c] : 0.f;
        d_W2bf[idx] = __float2bfloat16_rn(v);
    }
    if (idx < NLAYER*64*136){
        int l = idx/(64*136); int r = idx - l*64*136;
        int k = r/136, c = r - k*136;
        float v = (k<60 && c<128) ? ew1[(l*EINW + 265 + k)*Hd + c] : 0.f;
        d_Wdbf[idx] = __float2bfloat16_rn(v);
    }
}

// ---------------- per-node trig tables ----------------------------------------
__global__ void trig_kernel(const float* __restrict__ frac){
    int idx = blockIdx.x*blockDim.x + threadIdx.x;
    if (idx >= NN*30) return;
    int n = idx/30; int r = idx - n*30; int dd = r/10; int f = r - dd*10;
    float x = frac[n*3+dd];
    float th = 6.283185307179586f * (float)f * x;
    d_ts[idx] = sinf(th);
    d_tc[idx] = cosf(th);
}

// ---------------- latent ------------------------------------------------------
__global__ void __launch_bounds__(256) latent_kernel(
    const float* __restrict__ t, const int* __restrict__ atom_types,
    const int* __restrict__ node2graph, const float* __restrict__ xrd,
    const float* __restrict__ emb, const float* __restrict__ lw,
    const float* __restrict__ lb)
{
    __shared__ float sW[64*Hd];
    __shared__ float sX[48*64];
    int n0 = blockIdx.x*48;
    int tx = threadIdx.x;
    int warp = tx>>5, lane = tx&31, c0 = lane*4;
    float acc[6][4];
    #pragma unroll
    for (int e=0;e<6;e++){
        #pragma unroll
        for (int q=0;q<4;q++) acc[e][q] = lb[c0+q];
    }
    for (int kc=0;kc<6;kc++){
        for (int idx=tx; idx<64*Hd; idx+=256) sW[idx] = lw[kc*64*Hd + idx];
        for (int idx=tx; idx<48*64; idx+=256){
            int nl = idx>>6; int kk = idx&63; int k = kc*64+kk; int n = n0+nl;
            float v;
            if (k < 128)      v = emb[(atom_types[n]-1)*Hd + k];
            else if (k < 256) v = t[node2graph[n]*Hd + (k-128)];
            else              v = xrd[node2graph[n]*Hd + (k-256)];
            sX[idx] = v;
        }
        __syncthreads();
        #pragma unroll 4
        for (int kk=0;kk<64;kk++){
            float4 w4 = *(const float4*)&sW[kk*Hd + c0];
            #pragma unroll
            for (int e=0;e<6;e++){
                float xv = sX[(warp*6+e)*64 + kk];
                acc[e][0] += xv*w4.x; acc[e][1] += xv*w4.y;
                acc[e][2] += xv*w4.z; acc[e][3] += xv*w4.w;
            }
        }
        __syncthreads();
    }
    #pragma unroll
    for (int e=0;e<6;e++){
        float4 o = make_float4(acc[e][0],acc[e][1],acc[e][2],acc[e][3]);
        *(float4*)&d_h[(n0+warp*6+e)*Hd + c0] = o;
    }
}

// ---------------- lattice inner products --------------------------------------
__global__ void latips_kernel(const float* __restrict__ lat){
    int idx = blockIdx.x*blockDim.x + threadIdx.x;
    if (idx >= Gn*9) return;
    int g = idx/9; int rs = idx - g*9; int r = rs/3; int s = rs - r*3;
    const float* Lg = lat + g*9;
    d_latips[idx] = Lg[r*3]*Lg[s*3] + Lg[r*3+1]*Lg[s*3+1] + Lg[r*3+2]*Lg[s*3+2];
}

// ---------------- nodeproj layer 0 (tf32, 4 graphs/CTA) -----------------------
__global__ void __launch_bounds__(256) nodeproj_tc(const float* __restrict__ ew1, int l){
    extern __shared__ __align__(16) unsigned smu[];
    unsigned* sH = smu;              // [96][132]
    unsigned* sW = sH + 96*132;      // [128][264]
    int g0 = blockIdx.x*4;
    int tx = threadIdx.x;
    int warp = tx>>5, lane = tx&31;
    int gq = lane>>2, tg = lane&3;
    int wx = warp&3, wy = warp>>2;
    int m0 = wy*48, nbase = wx*64;

    for (int idx=tx; idx<96*Hd; idx+=256){
        int r = idx>>7, c = idx&127;
        sH[r*132+c] = tf32_rna(d_h[g0*24*Hd + idx]);
    }
    for (int idx=tx; idx<128*256; idx+=256){
        int k = idx>>8, n = idx&255;
        float v = (n<128) ? ew1[(l*EINW + k)*Hd + n]
                          : ew1[(l*EINW + 128 + k)*Hd + (n-128)];
        sW[k*264+n] = tf32_rna(v);
    }
    __syncthreads();

    float acc[3][8][4];
    #pragma unroll
    for (int mt=0;mt<3;mt++)
        #pragma unroll
        for (int nt=0;nt<8;nt++)
            #pragma unroll
            for (int q=0;q<4;q++) acc[mt][nt][q] = 0.f;

    #pragma unroll 4
    for (int kk=0;kk<16;kk++){
        int k0 = kk*8;
        unsigned ua[3][4], ub[8][2];
        #pragma unroll
        for (int mt=0;mt<3;mt++){
            int r = m0 + mt*16 + gq;
            ua[mt][0] = sH[r*132 + k0+tg];
            ua[mt][1] = sH[(r+8)*132 + k0+tg];
            ua[mt][2] = sH[r*132 + k0+tg+4];
            ua[mt][3] = sH[(r+8)*132 + k0+tg+4];
        }
        #pragma unroll
        for (int nt=0;nt<8;nt++){
            int c = nbase + nt*8 + gq;
            ub[nt][0] = sW[(k0+tg)*264 + c];
            ub[nt][1] = sW[(k0+tg+4)*264 + c];
        }
        #pragma unroll
        for (int mt=0;mt<3;mt++)
            #pragma unroll
            for (int nt=0;nt<8;nt++)
                mma8(acc[mt][nt], ua[mt], ub[nt]);
    }

    #pragma unroll
    for (int mt=0;mt<3;mt++){
        #pragma unroll
        for (int nt=0;nt<8;nt++){
            int c = nbase + nt*8 + tg*2;
            #pragma unroll
            for (int h=0;h<2;h++){
                int r = m0 + mt*16 + gq + h*8;
                float2 v = make_float2(acc[mt][nt][2*h+0], acc[mt][nt][2*h+1]);
                if (c < 128) *(float2*)&d_P[(g0*24+r)*Hd + c] = v;
                else         *(float2*)&d_Q[(g0*24+r)*Hd + (c-128)] = v;
            }
        }
    }
}

// ---------------- hot kernel: bf16 edge MLP, 2 CTAs/SM ------------------------
__global__ void __launch_bounds__(256,2) edge_kernel(
    const float* __restrict__ ew1, const float* __restrict__ eb1,
    const float* __restrict__ eb2, int l)
{
    extern __shared__ __align__(16) unsigned char smraw[];
    __nv_bfloat16* sW2h = (__nv_bfloat16*)smraw;     // [128][136]
    __nv_bfloat16* sWdh = sW2h + 17408;              // [64][136]
    __nv_bfloat16* sUh  = sWdh + 8704;               // [96][136]
    __nv_bfloat16* sFdh = sUh;                       // alias (disjoint lifetime)
    float* sP   = (float*)(sUh + 13056);             // [24][128] (latC folded in)
    float* sQ   = sP  + 3072;
    float* sS   = sQ  + 3072;
    float* sC   = sS  + 720;
    float* sLat = sC  + 720;
    float* sB2  = sLat + 128;

    int gr = blockIdx.x;
    int tx = threadIdx.x;
    int warp = tx>>5, lane = tx&31;
    int gq = lane>>2, tg = lane&3;
    int wx = warp&3, wy = warp>>2;
    int n0 = wx*32, m0 = wy*48;
    int row16 = lane & 15;
    int half8 = (lane & 16) ? 8 : 0;

    // ---- staging: bf16 weights as uint4 copies ----
    {
        const uint4* s2 = (const uint4*)&d_W2bf[l*128*136];
        uint4* t2 = (uint4*)sW2h;
        for (int i=tx; i<128*136/8; i+=256) t2[i] = s2[i];
        const uint4* sd = (const uint4*)&d_Wdbf[l*64*136];
        uint4* td = (uint4*)sWdh;
        for (int i=tx; i<64*136/8; i+=256) td[i] = sd[i];
    }
    for (int idx=tx; idx<24*Hd; idx+=256){
        sP[idx] = d_P[gr*24*Hd + idx];
        sQ[idx] = d_Q[gr*24*Hd + idx];
    }
    for (int idx=tx; idx<720; idx+=256){
        sS[idx] = d_ts[gr*720 + idx];
        sC[idx] = d_tc[gr*720 + idx];
    }
    if (tx < 128){
        float acc = eb1[l*Hd + tx];
        const float* wc = ew1 + (l*EINW + 256)*Hd;
        #pragma unroll
        for (int k=0;k<9;k++) acc += d_latips[gr*9+k] * wc[k*Hd + tx];
        sLat[tx] = acc;
        sB2[tx] = eb2[l*Hd + tx];
    }
    __syncthreads();
    // fold latC into sP
    for (int idx=tx; idx<24*Hd; idx+=256) sP[idx] += sLat[idx&127];
    __syncthreads();

    for (int it=0; it<6; ++it){
        int i0 = it*4;
        // ---- build Fd into the (free) U buffer ----
        for (int idx=tx; idx<96*72; idx+=256){
            int e = idx/72; int k = idx - e*72;
            float x = 0.f;
            if (k < 60){
                int s = e/24; int j = e - s*24; int i = i0+s;
                int df = (k<30) ? k : (k-30);
                float sj = sS[j*30+df], cj = sC[j*30+df];
                float si = sS[i*30+df], ci = sC[i*30+df];
                x = (k<30) ? (sj*ci - cj*si) : (cj*ci + sj*si);
            }
            sFdh[idx] = __float2bfloat16_rn(x);
        }
        __syncthreads();

        // ---- GEMM-A: Fd[96x64] @ Wd[64x128] ----
        float da[3][4][4];
        #pragma unroll
        for (int mt=0;mt<3;mt++)
            #pragma unroll
            for (int nt=0;nt<4;nt++)
                #pragma unroll
                for (int q=0;q<4;q++) da[mt][nt][q] = 0.f;
        #pragma unroll
        for (int kk=0;kk<4;kk++){
            int k0 = kk*16;
            unsigned ua[3][4], ub[4][2];
            #pragma unroll
            for (int mt=0;mt<3;mt++)
                ldsm4(ua[mt][0],ua[mt][1],ua[mt][2],ua[mt][3],
                      &sFdh[(m0+mt*16+row16)*72 + k0 + half8]);
            #pragma unroll
            for (int np=0;np<2;np++){
                unsigned t0,t1,t2,t3;
                ldsm4t(t0,t1,t2,t3, &sWdh[(k0+row16)*136 + n0+np*16 + half8]);
                ub[2*np][0]=t0; ub[2*np][1]=t1;
                ub[2*np+1][0]=t2; ub[2*np+1][1]=t3;
            }
            #pragma unroll
            for (int mt=0;mt<3;mt++)
                #pragma unroll
                for (int nt=0;nt<4;nt++)
                    mma16(da[mt][nt], ua[mt], ub[nt]);
        }
        __syncthreads();   // all Fd reads done before U overwrites the buffer

        // ---- epilogue A: +P[src](incl latC)+Q[dst], silu, bf16 U ----
        #pragma unroll
        for (int mt=0;mt<3;mt++){
            #pragma unroll
            for (int nt=0;nt<4;nt++){
                int c = n0 + nt*8 + tg*2;
                #pragma unroll
                for (int h=0; h<2; h++){
                    int r = m0 + mt*16 + gq + h*8;
                    int s = r/24; int j = r - s*24; int i = i0+s;
                    float base0 = sP[i*Hd+c]   + sQ[j*Hd+c];
                    float base1 = sP[i*Hd+c+1] + sQ[j*Hd+c+1];
                    float v0 = silu_f(da[mt][nt][2*h+0] + base0);
                    float v1 = silu_f(da[mt][nt][2*h+1] + base1);
                    *(unsigned*)&sUh[r*136 + c] = pack_bf2(v0, v1);
                }
            }
        }
        __syncthreads();

        // ---- GEMM-B: U[96x128] @ W2[128x128] ----
        float de[3][4][4];
        #pragma unroll
        for (int mt=0;mt<3;mt++)
            #pragma unroll
            for (int nt=0;nt<4;nt++)
                #pragma unroll
                for (int q=0;q<4;q++) de[mt][nt][q] = 0.f;
        #pragma unroll
        for (int kk=0;kk<8;kk++){
            int k0 = kk*16;
            unsigned ua[3][4], ub[4][2];
            #pragma unroll
            for (int mt=0;mt<3;mt++)
                ldsm4(ua[mt][0],ua[mt][1],ua[mt][2],ua[mt][3],
                      &sUh[(m0+mt*16+row16)*136 + k0 + half8]);
            #pragma unroll
            for (int np=0;np<2;np++){
                unsigned t0,t1,t2,t3;
                ldsm4t(t0,t1,t2,t3, &sW2h[(k0+row16)*136 + n0+np*16 + half8]);
                ub[2*np][0]=t0; ub[2*np][1]=t1;
                ub[2*np+1][0]=t2; ub[2*np+1][1]=t3;
            }
            #pragma unroll
            for (int mt=0;mt<3;mt++)
                #pragma unroll
                for (int nt=0;nt<4;nt++)
                    mma16(de[mt][nt], ua[mt], ub[nt]);
        }
        // ---- epilogue B: +b2, silu, shuffle scatter-mean ----
        int iA = i0 + wy*2, iB = iA + 1;
        #pragma unroll
        for (int nt=0;nt<4;nt++){
            #pragma unroll
            for (int qq=0;qq<2;qq++){
                int c = n0 + nt*8 + tg*2 + qq;
                float b = sB2[c];
                float s0 = silu_f(de[0][nt][qq]+b) + silu_f(de[0][nt][2+qq]+b)
                         + silu_f(de[1][nt][qq]+b);
                float s1 = silu_f(de[1][nt][2+qq]+b) + silu_f(de[2][nt][qq]+b)
                         + silu_f(de[2][nt][2+qq]+b);
                #pragma unroll
                for (int off=4;off<32;off<<=1){
                    s0 += __shfl_xor_sync(0xffffffffu, s0, off);
                    s1 += __shfl_xor_sync(0xffffffffu, s1, off);
                }
                if (gq == 0){
                    d_agg[(gr*24 + iA)*Hd + c] = s0 * (1.0f/24.0f);
                    d_agg[(gr*24 + iB)*Hd + c] = s1 * (1.0f/24.0f);
                }
            }
        }
        __syncthreads();
    }
}

// ---------------- fused node MLP + next-layer proj (tf32, 4 graphs/CTA) -------
__global__ void __launch_bounds__(256) node_fused(
    const float* __restrict__ nw1, const float* __restrict__ nb1,
    const float* __restrict__ nw2, const float* __restrict__ nb2,
    const float* __restrict__ ew1, int l, int do_proj)
{
    extern __shared__ __align__(16) unsigned smu[];
    unsigned* sX  = smu;               // [96][260]
    unsigned* sWb = sX + 96*260;       // [128][136]
    unsigned* sY  = sWb + 128*136;     // [96][132]
    float* sB = (float*)(sY + 96*132); // b1[128] | b2[128]
    unsigned* sH = sY;                 // proj-phase alias
    unsigned* sW = sX;                 // proj-phase alias ([128][264] spans sX..sWb)

    int g0 = blockIdx.x*4;
    int tx = threadIdx.x;
    int warp = tx>>5, lane = tx&31;
    int gq = lane>>2, tg = lane&3;
    int wx = warp&3, wy = warp>>2;
    int m0 = wy*48, n0 = wx*32;

    for (int idx=tx; idx<96*256; idx+=256){
        int r = idx>>8, k = idx&255;
        float v = (k<128) ? d_h[(g0*24+r)*Hd + k]
                          : d_agg[(g0*24+r)*Hd + (k-128)];
        sX[r*260+k] = tf32_rna(v);
    }
    if (tx < 128){ sB[tx] = nb1[l*Hd+tx]; sB[128+tx] = nb2[l*Hd+tx]; }

    const float* W1 = nw1 + l*256*Hd;
    float a1[3][4][4];
    #pragma unroll
    for (int mt=0;mt<3;mt++)
        #pragma unroll
        for (int nt=0;nt<4;nt++)
            #pragma unroll
            for (int q=0;q<4;q++) a1[mt][nt][q] = 0.f;

    for (int kc=0; kc<2; kc++){
        for (int idx=tx; idx<128*Hd; idx+=256){
            int k = idx>>7, c = idx&127;
            sWb[k*136+c] = tf32_rna(W1[(kc*128+k)*Hd + c]);
        }
        __syncthreads();
        #pragma unroll 4
        for (int kk=0;kk<16;kk++){
            int ka = kc*128 + kk*8;
            int kb = kk*8;
            unsigned ua[3][4], ub[4][2];
            #pragma unroll
            for (int mt=0;mt<3;mt++){
                int r = m0 + mt*16 + gq;
                ua[mt][0] = sX[r*260 + ka+tg];
                ua[mt][1] = sX[(r+8)*260 + ka+tg];
                ua[mt][2] = sX[r*260 + ka+tg+4];
                ua[mt][3] = sX[(r+8)*260 + ka+tg+4];
            }
            #pragma unroll
            for (int nt=0;nt<4;nt++){
                int c = n0 + nt*8 + gq;
                ub[nt][0] = sWb[(kb+tg)*136 + c];
                ub[nt][1] = sWb[(kb+tg+4)*136 + c];
            }
            #pragma unroll
            for (int mt=0;mt<3;mt++)
                #pragma unroll
                for (int nt=0;nt<4;nt++)
                    mma8(a1[mt][nt], ua[mt], ub[nt]);
        }
        __syncthreads();
    }

    // epilogue 1 -> tf32 Y ; then stage W2
    #pragma unroll
    for (int mt=0;mt<3;mt++){
        #pragma unroll
        for (int nt=0;nt<4;nt++){
            int c = n0 + nt*8 + tg*2;
            #pragma unroll
            for (int h=0;h<2;h++){
                int r = m0 + mt*16 + gq + h*8;
                sY[r*132 + c]   = tf32_rna(silu_f(a1[mt][nt][2*h+0] + sB[c]));
                sY[r*132 + c+1] = tf32_rna(silu_f(a1[mt][nt][2*h+1] + sB[c+1]));
            }
        }
    }
    const float* W2 = nw2 + l*Hd*Hd;
    for (int idx=tx; idx<Hd*Hd; idx+=256){
        int k = idx>>7, c = idx&127;
        sWb[k*136+c] = tf32_rna(W2[idx]);
    }
    __syncthreads();

    // GEMM2: [96x128] @ [128x128]
    float a2[3][4][4];
    #pragma unroll
    for (int mt=0;mt<3;mt++)
        #pragma unroll
        for (int nt=0;nt<4;nt++)
            #pragma unroll
            for (int q=0;q<4;q++) a2[mt][nt][q] = 0.f;
    #pragma unroll 4
    for (int kk=0;kk<16;kk++){
        int k0 = kk*8;
        unsigned ua[3][4], ub[4][2];
        #pragma unroll
        for (int mt=0;mt<3;mt++){
            int r = m0 + mt*16 + gq;
            ua[mt][0] = sY[r*132 + k0+tg];
            ua[mt][1] = sY[(r+8)*132 + k0+tg];
            ua[mt][2] = sY[r*132 + k0+tg+4];
            ua[mt][3] = sY[(r+8)*132 + k0+tg+4];
        }
        #pragma unroll
        for (int nt=0;nt<4;nt++){
            int c = n0 + nt*8 + gq;
            ub[nt][0] = sWb[(k0+tg)*136 + c];
            ub[nt][1] = sWb[(k0+tg+4)*136 + c];
        }
        #pragma unroll
        for (int mt=0;mt<3;mt++)
            #pragma unroll
            for (int nt=0;nt<4;nt++)
                mma8(a2[mt][nt], ua[mt], ub[nt]);
    }
    __syncthreads();   // all Y/W reads done before buffers are reused

    // epilogue 2: residual -> global h (+ tf32 h into sH for proj phase)
    float nh[3][4][4];
    #pragma unroll
    for (int mt=0;mt<3;mt++){
        #pragma unroll
        for (int nt=0;nt<4;nt++){
            int c = n0 + nt*8 + tg*2;
            #pragma unroll
            for (int h=0;h<2;h++){
                int r = m0 + mt*16 + gq + h*8;
                float o0 = silu_f(a2[mt][nt][2*h+0] + sB[128+c]);
                float o1 = silu_f(a2[mt][nt][2*h+1] + sB[128+c+1]);
                float2* p = (float2*)&d_h[(g0*24+r)*Hd + c];
                float2 old = *p;
                old.x += o0; old.y += o1;
                *p = old;
                nh[mt][nt][2*h+0] = old.x;
                nh[mt][nt][2*h+1] = old.y;
            }
        }
    }
    if (!do_proj) return;

    // ---- proj phase for layer l+1 ----
    #pragma unroll
    for (int mt=0;mt<3;mt++){
        #pragma unroll
        for (int nt=0;nt<4;nt++){
            int c = n0 + nt*8 + tg*2;
            #pragma unroll
            for (int h=0;h<2;h++){
                int r = m0 + mt*16 + gq + h*8;
                sH[r*132 + c]   = tf32_rna(nh[mt][nt][2*h+0]);
                sH[r*132 + c+1] = tf32_rna(nh[mt][nt][2*h+1]);
            }
        }
    }
    int lp = l+1;
    for (int idx=tx; idx<128*256; idx+=256){
        int k = idx>>8, n = idx&255;
        float v = (n<128) ? ew1[(lp*EINW + k)*Hd + n]
                          : ew1[(lp*EINW + 128 + k)*Hd + (n-128)];
        sW[k*264+n] = tf32_rna(v);
    }
    __syncthreads();

    int nbase = wx*64;
    float acc[3][8][4];
    #pragma unroll
    for (int mt=0;mt<3;mt++)
        #pragma unroll
        for (int nt=0;nt<8;nt++)
            #pragma unroll
            for (int q=0;q<4;q++) acc[mt][nt][q] = 0.f;

    #pragma unroll 4
    for (int kk=0;kk<16;kk++){
        int k0 = kk*8;
        unsigned ua[3][4], ub[8][2];
        #pragma unroll
        for (int mt=0;mt<3;mt++){
            int r = m0 + mt*16 + gq;
            ua[mt][0] = sH[r*132 + k0+tg];
            ua[mt][1] = sH[(r+8)*132 + k0+tg];
            ua[mt][2] = sH[r*132 + k0+tg+4];
            ua[mt][3] = sH[(r+8)*132 + k0+tg+4];
        }
        #pragma unroll
        for (int nt=0;nt<8;nt++){
            int c = nbase + nt*8 + gq;
            ub[nt][0] = sW[(k0+tg)*264 + c];
            ub[nt][1] = sW[(k0+tg+4)*264 + c];
        }
        #pragma unroll
        for (int mt=0;mt<3;mt++)
            #pragma unroll
            for (int nt=0;nt<8;nt++)
                mma8(acc[mt][nt], ua[mt], ub[nt]);
    }
    #pragma unroll
    for (int mt=0;mt<3;mt++){
        #pragma unroll
        for (int nt=0;nt<8;nt++){
            int c = nbase + nt*8 + tg*2;
            #pragma unroll
            for (int h=0;h<2;h++){
                int r = m0 + mt*16 + gq + h*8;
                float2 v = make_float2(acc[mt][nt][2*h+0], acc[mt][nt][2*h+1]);
                if (c < 128) *(float2*)&d_P[(g0*24+r)*Hd + c] = v;
                else         *(float2*)&d_Q[(g0*24+r)*Hd + (c-128)] = v;
            }
        }
    }
}

// ---------------- final heads -------------------------------------------------
__global__ void __launch_bounds__(128) final_kernel(
    const float* __restrict__ lat, const float* __restrict__ cw,
    const float* __restrict__ lw, float* __restrict__ out)
{
    __shared__ float sh[24*Hd];
    __shared__ float sgf[Hd];
    __shared__ float smid[9];
    __shared__ float scw[Hd*3];
    int g = blockIdx.x; int tx = threadIdx.x;
    for (int idx=tx; idx<24*Hd; idx+=128) sh[idx] = d_h[g*24*Hd + idx];
    for (int idx=tx; idx<Hd*3; idx+=128) scw[idx] = cw[idx];
    __syncthreads();
    {
        float acc = 0.f;
        #pragma unroll
        for (int a=0;a<24;a++) acc += sh[a*Hd + tx];
        sgf[tx] = acc * (1.0f/24.0f);
    }
    if (tx < 72){
        int n = tx/3; int dd = tx - n*3;
        float s = 0.f;
        #pragma unroll 4
        for (int k=0;k<Hd;k++) s += sh[n*Hd+k]*scw[k*3+dd];
        out[Gn*9 + (g*24+n)*3 + dd] = s;
    }
    __syncthreads();
    if (tx < 9){
        float s = 0.f;
        #pragma unroll 4
        for (int k=0;k<Hd;k++) s += sgf[k]*lw[k*9+tx];
        smid[tx] = s;
    }
    __syncthreads();
    if (tx < 9){
        int r = tx/3; int sc = tx - r*3;
        const float* Lg = lat + g*9;
        out[g*9+tx] = smid[r*3+0]*Lg[0+sc] + smid[r*3+1]*Lg[3+sc]
                    + smid[r*3+2]*Lg[6+sc];
    }
}

// ---------------- launch ------------------------------------------------------
extern "C" void kernel_launch(void* const* d_in, const int* in_sizes, int n_in,
                              void* d_out, int out_size)
{
    const float* t          = (const float*)d_in[0];
    const int*   atom_types = (const int*)  d_in[1];
    const float* frac       = (const float*)d_in[2];
    const float* lattices   = (const float*)d_in[3];
    const int*   node2graph = (const int*)  d_in[5];
    const float* xrd        = (const float*)d_in[6];
    const float* emb        = (const float*)d_in[7];
    const float* latent_w   = (const float*)d_in[8];
    const float* latent_b   = (const float*)d_in[9];
    const float* edge_w1    = (const float*)d_in[10];
    const float* edge_b1    = (const float*)d_in[11];
    const float* edge_w2    = (const float*)d_in[12];
    const float* edge_b2    = (const float*)d_in[13];
    const float* node_w1    = (const float*)d_in[14];
    const float* node_b1    = (const float*)d_in[15];
    const float* node_w2    = (const float*)d_in[16];
    const float* node_b2    = (const float*)d_in[17];
    const float* coord_w    = (const float*)d_in[18];
    const float* lattice_w  = (const float*)d_in[19];
    float* out = (float*)d_out;

    cudaFuncSetAttribute(edge_kernel,
        cudaFuncAttributeMaxDynamicSharedMemorySize, EDGE_SMEM_BYTES);
    cudaFuncSetAttribute(nodeproj_tc,
        cudaFuncAttributeMaxDynamicSharedMemorySize, NP_SMEM_BYTES);
    cudaFuncSetAttribute(node_fused,
        cudaFuncAttributeMaxDynamicSharedMemorySize, NF_SMEM_BYTES);

    trig_kernel<<<(NN*30 + 255)/256, 256>>>(frac);
    latent_kernel<<<NN/48, 256>>>(t, atom_types, node2graph, xrd,
                                  emb, latent_w, latent_b);
    latips_kernel<<<(Gn*9 + 255)/256, 256>>>(lattices);
    wconv_kernel<<<(NLAYER*128*136 + 255)/256, 256>>>(edge_w1, edge_w2);

    nodeproj_tc<<<Gn/4, 256, NP_SMEM_BYTES>>>(edge_w1, 0);
    for (int l=0; l<NLAYER; ++l){
        edge_kernel<<<Gn, 256, EDGE_SMEM_BYTES>>>(edge_w1, edge_b1, edge_b2, l);
        node_fused<<<Gn/4, 256, NF_SMEM_BYTES>>>(node_w1, node_b1,
                                                 node_w2, node_b2,
                                                 edge_w1, l, l < NLAYER-1);
    }

    final_kernel<<<Gn, 128>>>(lattices, coord_w, lattice_w, out);
}

// round 9
// speedup vs baseline: 4.1264x; 1.1334x over previous
#include <cuda_runtime.h>
#include <cuda_bf16.h>

#define Gn 512
#define An 24
#define Hd 128
#define NN (Gn*An)
#define NLAYER 4
#define EINW 325

// edge halves: W2 17408 | Wd(augmented) 13056 | U(alias Fd) 13056
// floats: S 720 | C 720 | Lat 128
#define EDGE_SMEM_BYTES ((17408+13056+13056)*2 + (720+720+128)*4)
#define NP_SMEM_BYTES ((96*132 + 128*264)*4)
#define NF_SMEM_BYTES ((96*260 + 128*136 + 96*132 + 256)*4)

// ---------------- scratch -----------------------------------------------------
__device__ float d_h[NN*Hd];
__device__ float d_P[NN*Hd];
__device__ float d_Q[NN*Hd];
__device__ float d_agg[NN*Hd];
__device__ float d_ts[NN*30];
__device__ float d_tc[NN*30];
__device__ float d_latips[Gn*9];
__device__ __align__(16) __nv_bfloat16 d_W2bf[NLAYER*128*136];
__device__ __align__(16) __nv_bfloat16 d_Wdbf[NLAYER*96*136];

__device__ __forceinline__ float silu_f(float x){
    return __fdividef(x, 1.0f + __expf(-x));
}

__device__ __forceinline__ unsigned pack_bf2(float lo, float hi){
    unsigned r;
    asm("cvt.rn.bf16x2.f32 %0, %1, %2;" : "=r"(r) : "f"(hi), "f"(lo));
    return r;
}

__device__ __forceinline__ unsigned tf32_rna(float x){
    unsigned u;
    asm("cvt.rna.tf32.f32 %0, %1;" : "=r"(u) : "f"(x));
    return u;
}

__device__ __forceinline__ void ldsm4(unsigned& r0, unsigned& r1, unsigned& r2,
                                      unsigned& r3, const void* p){
    unsigned a = (unsigned)__cvta_generic_to_shared(p);
    asm volatile("ldmatrix.sync.aligned.m8n8.x4.shared.b16 {%0,%1,%2,%3}, [%4];"
        : "=r"(r0), "=r"(r1), "=r"(r2), "=r"(r3) : "r"(a));
}

__device__ __forceinline__ void ldsm4t(unsigned& r0, unsigned& r1, unsigned& r2,
                                       unsigned& r3, const void* p){
    unsigned a = (unsigned)__cvta_generic_to_shared(p);
    asm volatile("ldmatrix.sync.aligned.m8n8.x4.trans.shared.b16 {%0,%1,%2,%3}, [%4];"
        : "=r"(r0), "=r"(r1), "=r"(r2), "=r"(r3) : "r"(a));
}

__device__ __forceinline__ void mma16(float* d, const unsigned* a, const unsigned* b){
    asm volatile(
        "mma.sync.aligned.m16n8k16.row.col.f32.bf16.bf16.f32 "
        "{%0,%1,%2,%3}, {%4,%5,%6,%7}, {%8,%9}, {%0,%1,%2,%3};\n"
        : "+f"(d[0]), "+f"(d[1]), "+f"(d[2]), "+f"(d[3])
        : "r"(a[0]), "r"(a[1]), "r"(a[2]), "r"(a[3]), "r"(b[0]), "r"(b[1]));
}

__device__ __forceinline__ void mma8(float* d, const unsigned* a, const unsigned* b){
    asm volatile(
        "mma.sync.aligned.m16n8k8.row.col.f32.tf32.tf32.f32 "
        "{%0,%1,%2,%3}, {%4,%5,%6,%7}, {%8,%9}, {%0,%1,%2,%3};\n"
        : "+f"(d[0]), "+f"(d[1]), "+f"(d[2]), "+f"(d[3])
        : "r"(a[0]), "r"(a[1]), "r"(a[2]), "r"(a[3]), "r"(b[0]), "r"(b[1]));
}

// ---------------- weight pre-conversion (bf16, padded) -------------------------
__global__ void wconv_kernel(const float* __restrict__ ew1,
                             const float* __restrict__ ew2){
    int idx = blockIdx.x*256 + threadIdx.x;
    if (idx < NLAYER*128*136){
        int l = idx/(128*136); int r = idx - l*128*136;
        int k = r/136, c = r - k*136;
        float v = (c<128) ? ew2[(l*128 + k)*Hd + c] : 0.f;
        d_W2bf[idx] = __float2bfloat16_rn(v);
    }
    if (idx < NLAYER*96*136){
        int l = idx/(96*136); int r = idx - l*96*136;
        int k = r/136, c = r - k*136;
        float v = (k<60 && c<128) ? ew1[(l*EINW + 265 + k)*Hd + c] : 0.f;
        d_Wdbf[idx] = __float2bfloat16_rn(v);
    }
}

// ---------------- per-node trig tables ----------------------------------------
__global__ void trig_kernel(const float* __restrict__ frac){
    int idx = blockIdx.x*blockDim.x + threadIdx.x;
    if (idx >= NN*30) return;
    int n = idx/30; int r = idx - n*30; int dd = r/10; int f = r - dd*10;
    float x = frac[n*3+dd];
    float th = 6.283185307179586f * (float)f * x;
    d_ts[idx] = sinf(th);
    d_tc[idx] = cosf(th);
}

// ---------------- latent ------------------------------------------------------
__global__ void __launch_bounds__(256) latent_kernel(
    const float* __restrict__ t, const int* __restrict__ atom_types,
    const int* __restrict__ node2graph, const float* __restrict__ xrd,
    const float* __restrict__ emb, const float* __restrict__ lw,
    const float* __restrict__ lb)
{
    __shared__ float sW[64*Hd];
    __shared__ float sX[48*64];
    int n0 = blockIdx.x*48;
    int tx = threadIdx.x;
    int warp = tx>>5, lane = tx&31, c0 = lane*4;
    float acc[6][4];
    #pragma unroll
    for (int e=0;e<6;e++){
        #pragma unroll
        for (int q=0;q<4;q++) acc[e][q] = lb[c0+q];
    }
    for (int kc=0;kc<6;kc++){
        for (int idx=tx; idx<64*Hd; idx+=256) sW[idx] = lw[kc*64*Hd + idx];
        for (int idx=tx; idx<48*64; idx+=256){
            int nl = idx>>6; int kk = idx&63; int k = kc*64+kk; int n = n0+nl;
            float v;
            if (k < 128)      v = emb[(atom_types[n]-1)*Hd + k];
            else if (k < 256) v = t[node2graph[n]*Hd + (k-128)];
            else              v = xrd[node2graph[n]*Hd + (k-256)];
            sX[idx] = v;
        }
        __syncthreads();
        #pragma unroll 4
        for (int kk=0;kk<64;kk++){
            float4 w4 = *(const float4*)&sW[kk*Hd + c0];
            #pragma unroll
            for (int e=0;e<6;e++){
                float xv = sX[(warp*6+e)*64 + kk];
                acc[e][0] += xv*w4.x; acc[e][1] += xv*w4.y;
                acc[e][2] += xv*w4.z; acc[e][3] += xv*w4.w;
            }
        }
        __syncthreads();
    }
    #pragma unroll
    for (int e=0;e<6;e++){
        float4 o = make_float4(acc[e][0],acc[e][1],acc[e][2],acc[e][3]);
        *(float4*)&d_h[(n0+warp*6+e)*Hd + c0] = o;
    }
}

// ---------------- lattice inner products --------------------------------------
__global__ void latips_kernel(const float* __restrict__ lat){
    int idx = blockIdx.x*blockDim.x + threadIdx.x;
    if (idx >= Gn*9) return;
    int g = idx/9; int rs = idx - g*9; int r = rs/3; int s = rs - r*3;
    const float* Lg = lat + g*9;
    d_latips[idx] = Lg[r*3]*Lg[s*3] + Lg[r*3+1]*Lg[s*3+1] + Lg[r*3+2]*Lg[s*3+2];
}

// ---------------- nodeproj layer 0 (tf32, 4 graphs/CTA) -----------------------
__global__ void __launch_bounds__(256) nodeproj_tc(const float* __restrict__ ew1, int l){
    extern __shared__ __align__(16) unsigned smu[];
    unsigned* sH = smu;              // [96][132]
    unsigned* sW = sH + 96*132;      // [128][264]
    int g0 = blockIdx.x*4;
    int tx = threadIdx.x;
    int warp = tx>>5, lane = tx&31;
    int gq = lane>>2, tg = lane&3;
    int wx = warp&3, wy = warp>>2;
    int m0 = wy*48, nbase = wx*64;

    for (int idx=tx; idx<96*Hd; idx+=256){
        int r = idx>>7, c = idx&127;
        sH[r*132+c] = tf32_rna(d_h[g0*24*Hd + idx]);
    }
    for (int idx=tx; idx<128*256; idx+=256){
        int k = idx>>8, n = idx&255;
        float v = (n<128) ? ew1[(l*EINW + k)*Hd + n]
                          : ew1[(l*EINW + 128 + k)*Hd + (n-128)];
        sW[k*264+n] = tf32_rna(v);
    }
    __syncthreads();

    float acc[3][8][4];
    #pragma unroll
    for (int mt=0;mt<3;mt++)
        #pragma unroll
        for (int nt=0;nt<8;nt++)
            #pragma unroll
            for (int q=0;q<4;q++) acc[mt][nt][q] = 0.f;

    #pragma unroll 4
    for (int kk=0;kk<16;kk++){
        int k0 = kk*8;
        unsigned ua[3][4], ub[8][2];
        #pragma unroll
        for (int mt=0;mt<3;mt++){
            int r = m0 + mt*16 + gq;
            ua[mt][0] = sH[r*132 + k0+tg];
            ua[mt][1] = sH[(r+8)*132 + k0+tg];
            ua[mt][2] = sH[r*132 + k0+tg+4];
            ua[mt][3] = sH[(r+8)*132 + k0+tg+4];
        }
        #pragma unroll
        for (int nt=0;nt<8;nt++){
            int c = nbase + nt*8 + gq;
            ub[nt][0] = sW[(k0+tg)*264 + c];
            ub[nt][1] = sW[(k0+tg+4)*264 + c];
        }
        #pragma unroll
        for (int mt=0;mt<3;mt++)
            #pragma unroll
            for (int nt=0;nt<8;nt++)
                mma8(acc[mt][nt], ua[mt], ub[nt]);
    }

    #pragma unroll
    for (int mt=0;mt<3;mt++){
        #pragma unroll
        for (int nt=0;nt<8;nt++){
            int c = nbase + nt*8 + tg*2;
            #pragma unroll
            for (int h=0;h<2;h++){
                int r = m0 + mt*16 + gq + h*8;
                float2 v = make_float2(acc[mt][nt][2*h+0], acc[mt][nt][2*h+1]);
                if (c < 128) *(float2*)&d_P[(g0*24+r)*Hd + c] = v;
                else         *(float2*)&d_Q[(g0*24+r)*Hd + (c-128)] = v;
            }
        }
    }
}

// ---------------- hot kernel: bf16 edge MLP, P/Q folded into GEMM-A -----------
__global__ void __launch_bounds__(256,2) edge_kernel(
    const float* __restrict__ ew1, const float* __restrict__ eb1,
    const float* __restrict__ eb2, int l)
{
    extern __shared__ __align__(16) unsigned char smraw[];
    __nv_bfloat16* sW2h = (__nv_bfloat16*)smraw;     // [128][136]
    __nv_bfloat16* sWdh = sW2h + 17408;              // [96][136]:
                                                     //   0-59 Wd | 60-63 P+lat (per tile)
                                                     //   64-87 Q | 88-95 zero
    __nv_bfloat16* sUh  = sWdh + 13056;              // [96][136]
    __nv_bfloat16* sFdh = sUh;                       // alias (disjoint lifetime)
    float* sS   = (float*)(sUh + 13056);             // [24][30]
    float* sC   = sS  + 720;
    float* sLat = sC  + 720;                         // [128]

    int gr = blockIdx.x;
    int tx = threadIdx.x;
    int warp = tx>>5, lane = tx&31;
    int gq = lane>>2, tg = lane&3;
    int wx = warp&3, wy = warp>>2;
    int n0 = wx*32, m0 = wy*48;
    int row16 = lane & 15;
    int half8 = (lane & 16) ? 8 : 0;

    // ---- staging ----
    {
        const uint4* s2 = (const uint4*)&d_W2bf[l*128*136];
        uint4* t2 = (uint4*)sW2h;
        for (int i=tx; i<128*136/8; i+=256) t2[i] = s2[i];
        const uint4* sd = (const uint4*)&d_Wdbf[l*96*136];
        uint4* td = (uint4*)sWdh;
        for (int i=tx; i<64*136/8; i+=256) td[i] = sd[i];          // rows 0-63
        for (int i=tx; i<8*136/8;  i+=256) td[1496+i] = sd[1496+i]; // rows 88-95 (zero)
    }
    // Q -> rows 64-87 (bf16)
    for (int idx=tx; idx<24*Hd; idx+=256){
        int j = idx>>7, c = idx&127;
        sWdh[(64+j)*136 + c] = __float2bfloat16_rn(d_Q[gr*24*Hd + idx]);
    }
    for (int idx=tx; idx<720; idx+=256){
        sS[idx] = d_ts[gr*720 + idx];
        sC[idx] = d_tc[gr*720 + idx];
    }
    if (tx < 128){
        float acc = eb1[l*Hd + tx];
        const float* wc = ew1 + (l*EINW + 256)*Hd;
        #pragma unroll
        for (int k=0;k<9;k++) acc += d_latips[gr*9+k] * wc[k*Hd + tx];
        sLat[tx] = acc;
    }
    // b2 -> registers (this thread's 8 epilogue-B columns)
    float rb2[8];
    #pragma unroll
    for (int nt=0;nt<4;nt++)
        #pragma unroll
        for (int qq=0;qq<2;qq++)
            rb2[nt*2+qq] = eb2[l*Hd + n0 + nt*8 + tg*2 + qq];
    __syncthreads();

    for (int it=0; it<6; ++it){
        int i0 = it*4;
        // ---- build Fd: trig pairs (cols 0-59) ----
        for (int idx=tx; idx<96*30; idx+=256){
            int e = idx/30; int df = idx - e*30;
            int s = e/24; int j = e - s*24; int i = i0+s;
            float sj = sS[j*30+df], cj = sC[j*30+df];
            float si = sS[i*30+df], ci = sC[i*30+df];
            sFdh[e*136 + df]      = __float2bfloat16_rn(sj*ci - cj*si);
            sFdh[e*136 + 30 + df] = __float2bfloat16_rn(cj*ci + sj*si);
        }
        // ---- Fd one-hot block (cols 60-95) ----
        for (int idx=tx; idx<96*36; idx+=256){
            int e = idx/36; int k = 60 + (idx - e*36);
            int s = e/24; int j = e - s*24;
            float v = (k == 60+s || k == 64+j) ? 1.f : 0.f;
            sFdh[e*136 + k] = __float2bfloat16_rn(v);
        }
        // ---- restage P+latC into sWdh rows 60-63 ----
        for (int idx=tx; idx<4*Hd; idx+=256){
            int s = idx>>7, c = idx&127;
            sWdh[(60+s)*136 + c] =
                __float2bfloat16_rn(d_P[(gr*24+i0+s)*Hd + c] + sLat[c]);
        }
        __syncthreads();

        // ---- GEMM-A: Fd[96x96] @ Wd_aug[96x128] (bias folded in) ----
        float da[3][4][4];
        #pragma unroll
        for (int mt=0;mt<3;mt++)
            #pragma unroll
            for (int nt=0;nt<4;nt++)
                #pragma unroll
                for (int q=0;q<4;q++) da[mt][nt][q] = 0.f;
        #pragma unroll
        for (int kk=0;kk<6;kk++){
            int k0 = kk*16;
            unsigned ua[3][4], ub[4][2];
            #pragma unroll
            for (int mt=0;mt<3;mt++)
                ldsm4(ua[mt][0],ua[mt][1],ua[mt][2],ua[mt][3],
                      &sFdh[(m0+mt*16+row16)*136 + k0 + half8]);
            #pragma unroll
            for (int np=0;np<2;np++){
                unsigned t0,t1,t2,t3;
                ldsm4t(t0,t1,t2,t3, &sWdh[(k0+row16)*136 + n0+np*16 + half8]);
                ub[2*np][0]=t0; ub[2*np][1]=t1;
                ub[2*np+1][0]=t2; ub[2*np+1][1]=t3;
            }
            #pragma unroll
            for (int mt=0;mt<3;mt++)
                #pragma unroll
                for (int nt=0;nt<4;nt++)
                    mma16(da[mt][nt], ua[mt], ub[nt]);
        }
        __syncthreads();   // Fd reads done before U overwrites the buffer

        // ---- epilogue A: silu only ----
        #pragma unroll
        for (int mt=0;mt<3;mt++){
            #pragma unroll
            for (int nt=0;nt<4;nt++){
                int c = n0 + nt*8 + tg*2;
                #pragma unroll
                for (int h=0; h<2; h++){
                    int r = m0 + mt*16 + gq + h*8;
                    float v0 = silu_f(da[mt][nt][2*h+0]);
                    float v1 = silu_f(da[mt][nt][2*h+1]);
                    *(unsigned*)&sUh[r*136 + c] = pack_bf2(v0, v1);
                }
            }
        }
        __syncthreads();

        // ---- GEMM-B: U[96x128] @ W2[128x128] ----
        float de[3][4][4];
        #pragma unroll
        for (int mt=0;mt<3;mt++)
            #pragma unroll
            for (int nt=0;nt<4;nt++)
                #pragma unroll
                for (int q=0;q<4;q++) de[mt][nt][q] = 0.f;
        #pragma unroll
        for (int kk=0;kk<8;kk++){
            int k0 = kk*16;
            unsigned ua[3][4], ub[4][2];
            #pragma unroll
            for (int mt=0;mt<3;mt++)
                ldsm4(ua[mt][0],ua[mt][1],ua[mt][2],ua[mt][3],
                      &sUh[(m0+mt*16+row16)*136 + k0 + half8]);
            #pragma unroll
            for (int np=0;np<2;np++){
                unsigned t0,t1,t2,t3;
                ldsm4t(t0,t1,t2,t3, &sW2h[(k0+row16)*136 + n0+np*16 + half8]);
                ub[2*np][0]=t0; ub[2*np][1]=t1;
                ub[2*np+1][0]=t2; ub[2*np+1][1]=t3;
            }
            #pragma unroll
            for (int mt=0;mt<3;mt++)
                #pragma unroll
                for (int nt=0;nt<4;nt++)
                    mma16(de[mt][nt], ua[mt], ub[nt]);
        }
        // ---- epilogue B: +b2(regs), silu, shuffle scatter-mean ----
        int iA = i0 + wy*2, iB = iA + 1;
        #pragma unroll
        for (int nt=0;nt<4;nt++){
            #pragma unroll
            for (int qq=0;qq<2;qq++){
                int c = n0 + nt*8 + tg*2 + qq;
                float b = rb2[nt*2+qq];
                float s0 = silu_f(de[0][nt][qq]+b) + silu_f(de[0][nt][2+qq]+b)
                         + silu_f(de[1][nt][qq]+b);
                float s1 = silu_f(de[1][nt][2+qq]+b) + silu_f(de[2][nt][qq]+b)
                         + silu_f(de[2][nt][2+qq]+b);
                #pragma unroll
                for (int off=4;off<32;off<<=1){
                    s0 += __shfl_xor_sync(0xffffffffu, s0, off);
                    s1 += __shfl_xor_sync(0xffffffffu, s1, off);
                }
                if (gq == 0){
                    d_agg[(gr*24 + iA)*Hd + c] = s0 * (1.0f/24.0f);
                    d_agg[(gr*24 + iB)*Hd + c] = s1 * (1.0f/24.0f);
                }
            }
        }
        __syncthreads();
    }
}

// ---------------- fused node MLP + next-layer proj (tf32, 4 graphs/CTA) -------
__global__ void __launch_bounds__(256) node_fused(
    const float* __restrict__ nw1, const float* __restrict__ nb1,
    const float* __restrict__ nw2, const float* __restrict__ nb2,
    const float* __restrict__ ew1, int l, int do_proj)
{
    extern __shared__ __align__(16) unsigned smu[];
    unsigned* sX  = smu;               // [96][260]
    unsigned* sWb = sX + 96*260;       // [128][136]
    unsigned* sY  = sWb + 128*136;     // [96][132]
    float* sB = (float*)(sY + 96*132); // b1[128] | b2[128]
    unsigned* sH = sY;                 // proj-phase alias
    unsigned* sW = sX;                 // proj-phase alias ([128][264] spans sX..sWb)

    int g0 = blockIdx.x*4;
    int tx = threadIdx.x;
    int warp = tx>>5, lane = tx&31;
    int gq = lane>>2, tg = lane&3;
    int wx = warp&3, wy = warp>>2;
    int m0 = wy*48, n0 = wx*32;

    for (int idx=tx; idx<96*256; idx+=256){
        int r = idx>>8, k = idx&255;
        float v = (k<128) ? d_h[(g0*24+r)*Hd + k]
                          : d_agg[(g0*24+r)*Hd + (k-128)];
        sX[r*260+k] = tf32_rna(v);
    }
    if (tx < 128){ sB[tx] = nb1[l*Hd+tx]; sB[128+tx] = nb2[l*Hd+tx]; }

    const float* W1 = nw1 + l*256*Hd;
    float a1[3][4][4];
    #pragma unroll
    for (int mt=0;mt<3;mt++)
        #pragma unroll
        for (int nt=0;nt<4;nt++)
            #pragma unroll
            for (int q=0;q<4;q++) a1[mt][nt][q] = 0.f;

    for (int kc=0; kc<2; kc++){
        for (int idx=tx; idx<128*Hd; idx+=256){
            int k = idx>>7, c = idx&127;
            sWb[k*136+c] = tf32_rna(W1[(kc*128+k)*Hd + c]);
        }
        __syncthreads();
        #pragma unroll 4
        for (int kk=0;kk<16;kk++){
            int ka = kc*128 + kk*8;
            int kb = kk*8;
            unsigned ua[3][4], ub[4][2];
            #pragma unroll
            for (int mt=0;mt<3;mt++){
                int r = m0 + mt*16 + gq;
                ua[mt][0] = sX[r*260 + ka+tg];
                ua[mt][1] = sX[(r+8)*260 + ka+tg];
                ua[mt][2] = sX[r*260 + ka+tg+4];
                ua[mt][3] = sX[(r+8)*260 + ka+tg+4];
            }
            #pragma unroll
            for (int nt=0;nt<4;nt++){
                int c = n0 + nt*8 + gq;
                ub[nt][0] = sWb[(kb+tg)*136 + c];
                ub[nt][1] = sWb[(kb+tg+4)*136 + c];
            }
            #pragma unroll
            for (int mt=0;mt<3;mt++)
                #pragma unroll
                for (int nt=0;nt<4;nt++)
                    mma8(a1[mt][nt], ua[mt], ub[nt]);
        }
        __syncthreads();
    }

    // epilogue 1 -> tf32 Y ; then stage W2
    #pragma unroll
    for (int mt=0;mt<3;mt++){
        #pragma unroll
        for (int nt=0;nt<4;nt++){
            int c = n0 + nt*8 + tg*2;
            #pragma unroll
            for (int h=0;h<2;h++){
                int r = m0 + mt*16 + gq + h*8;
                sY[r*132 + c]   = tf32_rna(silu_f(a1[mt][nt][2*h+0] + sB[c]));
                sY[r*132 + c+1] = tf32_rna(silu_f(a1[mt][nt][2*h+1] + sB[c+1]));
            }
        }
    }
    const float* W2 = nw2 + l*Hd*Hd;
    for (int idx=tx; idx<Hd*Hd; idx+=256){
        int k = idx>>7, c = idx&127;
        sWb[k*136+c] = tf32_rna(W2[idx]);
    }
    __syncthreads();

    // GEMM2: [96x128] @ [128x128]
    float a2[3][4][4];
    #pragma unroll
    for (int mt=0;mt<3;mt++)
        #pragma unroll
        for (int nt=0;nt<4;nt++)
            #pragma unroll
            for (int q=0;q<4;q++) a2[mt][nt][q] = 0.f;
    #pragma unroll 4
    for (int kk=0;kk<16;kk++){
        int k0 = kk*8;
        unsigned ua[3][4], ub[4][2];
        #pragma unroll
        for (int mt=0;mt<3;mt++){
            int r = m0 + mt*16 + gq;
            ua[mt][0] = sY[r*132 + k0+tg];
            ua[mt][1] = sY[(r+8)*132 + k0+tg];
            ua[mt][2] = sY[r*132 + k0+tg+4];
            ua[mt][3] = sY[(r+8)*132 + k0+tg+4];
        }
        #pragma unroll
        for (int nt=0;nt<4;nt++){
            int c = n0 + nt*8 + gq;
            ub[nt][0] = sWb[(k0+tg)*136 + c];
            ub[nt][1] = sWb[(k0+tg+4)*136 + c];
        }
        #pragma unroll
        for (int mt=0;mt<3;mt++)
            #pragma unroll
            for (int nt=0;nt<4;nt++)
                mma8(a2[mt][nt], ua[mt], ub[nt]);
    }
    __syncthreads();   // all Y/W reads done before buffers are reused

    // epilogue 2: residual -> global h (+ tf32 h for proj phase)
    float nh[3][4][4];
    #pragma unroll
    for (int mt=0;mt<3;mt++){
        #pragma unroll
        for (int nt=0;nt<4;nt++){
            int c = n0 + nt*8 + tg*2;
            #pragma unroll
            for (int h=0;h<2;h++){
                int r = m0 + mt*16 + gq + h*8;
                float o0 = silu_f(a2[mt][nt][2*h+0] + sB[128+c]);
                float o1 = silu_f(a2[mt][nt][2*h+1] + sB[128+c+1]);
                float2* p = (float2*)&d_h[(g0*24+r)*Hd + c];
                float2 old = *p;
                old.x += o0; old.y += o1;
                *p = old;
                nh[mt][nt][2*h+0] = old.x;
                nh[mt][nt][2*h+1] = old.y;
            }
        }
    }
    if (!do_proj) return;

    // ---- proj phase for layer l+1 ----
    #pragma unroll
    for (int mt=0;mt<3;mt++){
        #pragma unroll
        for (int nt=0;nt<4;nt++){
            int c = n0 + nt*8 + tg*2;
            #pragma unroll
            for (int h=0;h<2;h++){
                int r = m0 + mt*16 + gq + h*8;
                sH[r*132 + c]   = tf32_rna(nh[mt][nt][2*h+0]);
                sH[r*132 + c+1] = tf32_rna(nh[mt][nt][2*h+1]);
            }
        }
    }
    int lp = l+1;
    for (int idx=tx; idx<128*256; idx+=256){
        int k = idx>>8, n = idx&255;
        float v = (n<128) ? ew1[(lp*EINW + k)*Hd + n]
                          : ew1[(lp*EINW + 128 + k)*Hd + (n-128)];
        sW[k*264+n] = tf32_rna(v);
    }
    __syncthreads();

    int nbase = wx*64;
    float acc[3][8][4];
    #pragma unroll
    for (int mt=0;mt<3;mt++)
        #pragma unroll
        for (int nt=0;nt<8;nt++)
            #pragma unroll
            for (int q=0;q<4;q++) acc[mt][nt][q] = 0.f;

    #pragma unroll 4
    for (int kk=0;kk<16;kk++){
        int k0 = kk*8;
        unsigned ua[3][4], ub[8][2];
        #pragma unroll
        for (int mt=0;mt<3;mt++){
            int r = m0 + mt*16 + gq;
            ua[mt][0] = sH[r*132 + k0+tg];
            ua[mt][1] = sH[(r+8)*132 + k0+tg];
            ua[mt][2] = sH[r*132 + k0+tg+4];
            ua[mt][3] = sH[(r+8)*132 + k0+tg+4];
        }
        #pragma unroll
        for (int nt=0;nt<8;nt++){
            int c = nbase + nt*8 + gq;
            ub[nt][0] = sW[(k0+tg)*264 + c];
            ub[nt][1] = sW[(k0+tg+4)*264 + c];
        }
        #pragma unroll
        for (int mt=0;mt<3;mt++)
            #pragma unroll
            for (int nt=0;nt<8;nt++)
                mma8(acc[mt][nt], ua[mt], ub[nt]);
    }
    #pragma unroll
    for (int mt=0;mt<3;mt++){
        #pragma unroll
        for (int nt=0;nt<8;nt++){
            int c = nbase + nt*8 + tg*2;
            #pragma unroll
            for (int h=0;h<2;h++){
                int r = m0 + mt*16 + gq + h*8;
                float2 v = make_float2(acc[mt][nt][2*h+0], acc[mt][nt][2*h+1]);
                if (c < 128) *(float2*)&d_P[(g0*24+r)*Hd + c] = v;
                else         *(float2*)&d_Q[(g0*24+r)*Hd + (c-128)] = v;
            }
        }
    }
}

// ---------------- final heads -------------------------------------------------
__global__ void __launch_bounds__(128) final_kernel(
    const float* __restrict__ lat, const float* __restrict__ cw,
    const float* __restrict__ lw, float* __restrict__ out)
{
    __shared__ float sh[24*Hd];
    __shared__ float sgf[Hd];
    __shared__ float smid[9];
    __shared__ float scw[Hd*3];
    int g = blockIdx.x; int tx = threadIdx.x;
    for (int idx=tx; idx<24*Hd; idx+=128) sh[idx] = d_h[g*24*Hd + idx];
    for (int idx=tx; idx<Hd*3; idx+=128) scw[idx] = cw[idx];
    __syncthreads();
    {
        float acc = 0.f;
        #pragma unroll
        for (int a=0;a<24;a++) acc += sh[a*Hd + tx];
        sgf[tx] = acc * (1.0f/24.0f);
    }
    if (tx < 72){
        int n = tx/3; int dd = tx - n*3;
        float s = 0.f;
        #pragma unroll 4
        for (int k=0;k<Hd;k++) s += sh[n*Hd+k]*scw[k*3+dd];
        out[Gn*9 + (g*24+n)*3 + dd] = s;
    }
    __syncthreads();
    if (tx < 9){
        float s = 0.f;
        #pragma unroll 4
        for (int k=0;k<Hd;k++) s += sgf[k]*lw[k*9+tx];
        smid[tx] = s;
    }
    __syncthreads();
    if (tx < 9){
        int r = tx/3; int sc = tx - r*3;
        const float* Lg = lat + g*9;
        out[g*9+tx] = smid[r*3+0]*Lg[0+sc] + smid[r*3+1]*Lg[3+sc]
                    + smid[r*3+2]*Lg[6+sc];
    }
}

// ---------------- launch ------------------------------------------------------
extern "C" void kernel_launch(void* const* d_in, const int* in_sizes, int n_in,
                              void* d_out, int out_size)
{
    const float* t          = (const float*)d_in[0];
    const int*   atom_types = (const int*)  d_in[1];
    const float* frac       = (const float*)d_in[2];
    const float* lattices   = (const float*)d_in[3];
    const int*   node2graph = (const int*)  d_in[5];
    const float* xrd        = (const float*)d_in[6];
    const float* emb        = (const float*)d_in[7];
    const float* latent_w   = (const float*)d_in[8];
    const float* latent_b   = (const float*)d_in[9];
    const float* edge_w1    = (const float*)d_in[10];
    const float* edge_b1    = (const float*)d_in[11];
    const float* edge_w2    = (const float*)d_in[12];
    const float* edge_b2    = (const float*)d_in[13];
    const float* node_w1    = (const float*)d_in[14];
    const float* node_b1    = (const float*)d_in[15];
    const float* node_w2    = (const float*)d_in[16];
    const float* node_b2    = (const float*)d_in[17];
    const float* coord_w    = (const float*)d_in[18];
    const float* lattice_w  = (const float*)d_in[19];
    float* out = (float*)d_out;

    cudaFuncSetAttribute(edge_kernel,
        cudaFuncAttributeMaxDynamicSharedMemorySize, EDGE_SMEM_BYTES);
    cudaFuncSetAttribute(nodeproj_tc,
        cudaFuncAttributeMaxDynamicSharedMemorySize, NP_SMEM_BYTES);
    cudaFuncSetAttribute(node_fused,
        cudaFuncAttributeMaxDynamicSharedMemorySize, NF_SMEM_BYTES);

    trig_kernel<<<(NN*30 + 255)/256, 256>>>(frac);
    latent_kernel<<<NN/48, 256>>>(t, atom_types, node2graph, xrd,
                                  emb, latent_w, latent_b);
    latips_kernel<<<(Gn*9 + 255)/256, 256>>>(lattices);
    wconv_kernel<<<(NLAYER*128*136 + 255)/256, 256>>>(edge_w1, edge_w2);

    nodeproj_tc<<<Gn/4, 256, NP_SMEM_BYTES>>>(edge_w1, 0);
    for (int l=0; l<NLAYER; ++l){
        edge_kernel<<<Gn, 256, EDGE_SMEM_BYTES>>>(edge_w1, edge_b1, edge_b2, l);
        node_fused<<<Gn/4, 256, NF_SMEM_BYTES>>>(node_w1, node_b1,
                                                 node_w2, node_b2,
                                                 edge_w1, l, l < NLAYER-1);
    }

    final_kernel<<<Gn, 128>>>(lattices, coord_w, lattice_w, out);
}

// round 10
// speedup vs baseline: 4.2494x; 1.0298x over previous
#include <cuda_runtime.h>
#include <cuda_bf16.h>

#define Gn 512
#define An 24
#define Hd 128
#define NN (Gn*An)
#define NLAYER 4
#define EINW 325

// edge halves: W2 17408 | Wd(augmented) 13056 | U(alias Fd) 13056
// floats: S 720 | C 720 | Lat 128
#define EDGE_SMEM_BYTES ((17408+13056+13056)*2 + (720+720+128)*4)
#define NP_SMEM_BYTES ((96*132 + 128*264)*4)
// node_fused (48 rows/CTA): sX [48][260] | chunk 8704 u32 | sY [48][132] | bias
#define NF_SMEM_BYTES ((48*260 + 8704 + 48*132)*4 + 1024)

// ---------------- scratch -----------------------------------------------------
__device__ float d_h[NN*Hd];
__device__ float d_P[NN*Hd];
__device__ float d_Q[NN*Hd];
__device__ float d_agg[NN*Hd];
__device__ float d_ts[NN*30];
__device__ float d_tc[NN*30];
__device__ float d_latips[Gn*9];
__device__ __align__(16) __nv_bfloat16 d_W2bf[NLAYER*128*136];
__device__ __align__(16) __nv_bfloat16 d_Wdbf[NLAYER*96*136];

__device__ __forceinline__ float silu_f(float x){
    return __fdividef(x, 1.0f + __expf(-x));
}

__device__ __forceinline__ unsigned pack_bf2(float lo, float hi){
    unsigned r;
    asm("cvt.rn.bf16x2.f32 %0, %1, %2;" : "=r"(r) : "f"(hi), "f"(lo));
    return r;
}

__device__ __forceinline__ unsigned tf32_rna(float x){
    unsigned u;
    asm("cvt.rna.tf32.f32 %0, %1;" : "=r"(u) : "f"(x));
    return u;
}

__device__ __forceinline__ void ldsm4(unsigned& r0, unsigned& r1, unsigned& r2,
                                      unsigned& r3, const void* p){
    unsigned a = (unsigned)__cvta_generic_to_shared(p);
    asm volatile("ldmatrix.sync.aligned.m8n8.x4.shared.b16 {%0,%1,%2,%3}, [%4];"
        : "=r"(r0), "=r"(r1), "=r"(r2), "=r"(r3) : "r"(a));
}

__device__ __forceinline__ void ldsm4t(unsigned& r0, unsigned& r1, unsigned& r2,
                                       unsigned& r3, const void* p){
    unsigned a = (unsigned)__cvta_generic_to_shared(p);
    asm volatile("ldmatrix.sync.aligned.m8n8.x4.trans.shared.b16 {%0,%1,%2,%3}, [%4];"
        : "=r"(r0), "=r"(r1), "=r"(r2), "=r"(r3) : "r"(a));
}

__device__ __forceinline__ void mma16(float* d, const unsigned* a, const unsigned* b){
    asm volatile(
        "mma.sync.aligned.m16n8k16.row.col.f32.bf16.bf16.f32 "
        "{%0,%1,%2,%3}, {%4,%5,%6,%7}, {%8,%9}, {%0,%1,%2,%3};\n"
        : "+f"(d[0]), "+f"(d[1]), "+f"(d[2]), "+f"(d[3])
        : "r"(a[0]), "r"(a[1]), "r"(a[2]), "r"(a[3]), "r"(b[0]), "r"(b[1]));
}

__device__ __forceinline__ void mma8(float* d, const unsigned* a, const unsigned* b){
    asm volatile(
        "mma.sync.aligned.m16n8k8.row.col.f32.tf32.tf32.f32 "
        "{%0,%1,%2,%3}, {%4,%5,%6,%7}, {%8,%9}, {%0,%1,%2,%3};\n"
        : "+f"(d[0]), "+f"(d[1]), "+f"(d[2]), "+f"(d[3])
        : "r"(a[0]), "r"(a[1]), "r"(a[2]), "r"(a[3]), "r"(b[0]), "r"(b[1]));
}

// ---------------- weight pre-conversion (bf16, padded) -------------------------
__global__ void wconv_kernel(const float* __restrict__ ew1,
                             const float* __restrict__ ew2){
    int idx = blockIdx.x*256 + threadIdx.x;
    if (idx < NLAYER*128*136){
        int l = idx/(128*136); int r = idx - l*128*136;
        int k = r/136, c = r - k*136;
        float v = (c<128) ? ew2[(l*128 + k)*Hd + c] : 0.f;
        d_W2bf[idx] = __float2bfloat16_rn(v);
    }
    if (idx < NLAYER*96*136){
        int l = idx/(96*136); int r = idx - l*96*136;
        int k = r/136, c = r - k*136;
        float v = (k<60 && c<128) ? ew1[(l*EINW + 265 + k)*Hd + c] : 0.f;
        d_Wdbf[idx] = __float2bfloat16_rn(v);
    }
}

// ---------------- per-node trig tables ----------------------------------------
__global__ void trig_kernel(const float* __restrict__ frac){
    int idx = blockIdx.x*blockDim.x + threadIdx.x;
    if (idx >= NN*30) return;
    int n = idx/30; int r = idx - n*30; int dd = r/10; int f = r - dd*10;
    float x = frac[n*3+dd];
    float th = 6.283185307179586f * (float)f * x;
    d_ts[idx] = sinf(th);
    d_tc[idx] = cosf(th);
}

// ---------------- latent ------------------------------------------------------
__global__ void __launch_bounds__(256) latent_kernel(
    const float* __restrict__ t, const int* __restrict__ atom_types,
    const int* __restrict__ node2graph, const float* __restrict__ xrd,
    const float* __restrict__ emb, const float* __restrict__ lw,
    const float* __restrict__ lb)
{
    __shared__ float sW[64*Hd];
    __shared__ float sX[48*64];
    int n0 = blockIdx.x*48;
    int tx = threadIdx.x;
    int warp = tx>>5, lane = tx&31, c0 = lane*4;
    float acc[6][4];
    #pragma unroll
    for (int e=0;e<6;e++){
        #pragma unroll
        for (int q=0;q<4;q++) acc[e][q] = lb[c0+q];
    }
    for (int kc=0;kc<6;kc++){
        for (int idx=tx; idx<64*Hd; idx+=256) sW[idx] = lw[kc*64*Hd + idx];
        for (int idx=tx; idx<48*64; idx+=256){
            int nl = idx>>6; int kk = idx&63; int k = kc*64+kk; int n = n0+nl;
            float v;
            if (k < 128)      v = emb[(atom_types[n]-1)*Hd + k];
            else if (k < 256) v = t[node2graph[n]*Hd + (k-128)];
            else              v = xrd[node2graph[n]*Hd + (k-256)];
            sX[idx] = v;
        }
        __syncthreads();
        #pragma unroll 4
        for (int kk=0;kk<64;kk++){
            float4 w4 = *(const float4*)&sW[kk*Hd + c0];
            #pragma unroll
            for (int e=0;e<6;e++){
                float xv = sX[(warp*6+e)*64 + kk];
                acc[e][0] += xv*w4.x; acc[e][1] += xv*w4.y;
                acc[e][2] += xv*w4.z; acc[e][3] += xv*w4.w;
            }
        }
        __syncthreads();
    }
    #pragma unroll
    for (int e=0;e<6;e++){
        float4 o = make_float4(acc[e][0],acc[e][1],acc[e][2],acc[e][3]);
        *(float4*)&d_h[(n0+warp*6+e)*Hd + c0] = o;
    }
}

// ---------------- lattice inner products --------------------------------------
__global__ void latips_kernel(const float* __restrict__ lat){
    int idx = blockIdx.x*blockDim.x + threadIdx.x;
    if (idx >= Gn*9) return;
    int g = idx/9; int rs = idx - g*9; int r = rs/3; int s = rs - r*3;
    const float* Lg = lat + g*9;
    d_latips[idx] = Lg[r*3]*Lg[s*3] + Lg[r*3+1]*Lg[s*3+1] + Lg[r*3+2]*Lg[s*3+2];
}

// ---------------- nodeproj layer 0 (tf32, 4 graphs/CTA) -----------------------
__global__ void __launch_bounds__(256) nodeproj_tc(const float* __restrict__ ew1, int l){
    extern __shared__ __align__(16) unsigned smu[];
    unsigned* sH = smu;              // [96][132]
    unsigned* sW = sH + 96*132;      // [128][264]
    int g0 = blockIdx.x*4;
    int tx = threadIdx.x;
    int warp = tx>>5, lane = tx&31;
    int gq = lane>>2, tg = lane&3;
    int wx = warp&3, wy = warp>>2;
    int m0 = wy*48, nbase = wx*64;

    for (int idx=tx; idx<96*Hd; idx+=256){
        int r = idx>>7, c = idx&127;
        sH[r*132+c] = tf32_rna(d_h[g0*24*Hd + idx]);
    }
    for (int idx=tx; idx<128*256; idx+=256){
        int k = idx>>8, n = idx&255;
        float v = (n<128) ? ew1[(l*EINW + k)*Hd + n]
                          : ew1[(l*EINW + 128 + k)*Hd + (n-128)];
        sW[k*264+n] = tf32_rna(v);
    }
    __syncthreads();

    float acc[3][8][4];
    #pragma unroll
    for (int mt=0;mt<3;mt++)
        #pragma unroll
        for (int nt=0;nt<8;nt++)
            #pragma unroll
            for (int q=0;q<4;q++) acc[mt][nt][q] = 0.f;

    #pragma unroll 4
    for (int kk=0;kk<16;kk++){
        int k0 = kk*8;
        unsigned ua[3][4], ub[8][2];
        #pragma unroll
        for (int mt=0;mt<3;mt++){
            int r = m0 + mt*16 + gq;
            ua[mt][0] = sH[r*132 + k0+tg];
            ua[mt][1] = sH[(r+8)*132 + k0+tg];
            ua[mt][2] = sH[r*132 + k0+tg+4];
            ua[mt][3] = sH[(r+8)*132 + k0+tg+4];
        }
        #pragma unroll
        for (int nt=0;nt<8;nt++){
            int c = nbase + nt*8 + gq;
            ub[nt][0] = sW[(k0+tg)*264 + c];
            ub[nt][1] = sW[(k0+tg+4)*264 + c];
        }
        #pragma unroll
        for (int mt=0;mt<3;mt++)
            #pragma unroll
            for (int nt=0;nt<8;nt++)
                mma8(acc[mt][nt], ua[mt], ub[nt]);
    }

    #pragma unroll
    for (int mt=0;mt<3;mt++){
        #pragma unroll
        for (int nt=0;nt<8;nt++){
            int c = nbase + nt*8 + tg*2;
            #pragma unroll
            for (int h=0;h<2;h++){
                int r = m0 + mt*16 + gq + h*8;
                float2 v = make_float2(acc[mt][nt][2*h+0], acc[mt][nt][2*h+1]);
                if (c < 128) *(float2*)&d_P[(g0*24+r)*Hd + c] = v;
                else         *(float2*)&d_Q[(g0*24+r)*Hd + (c-128)] = v;
            }
        }
    }
}

// ---------------- hot kernel: persistent bf16 edge MLP (2 graphs/CTA) ---------
__global__ void __launch_bounds__(256,2) edge_kernel(
    const float* __restrict__ ew1, const float* __restrict__ eb1,
    const float* __restrict__ eb2, int l)
{
    extern __shared__ __align__(16) unsigned char smraw[];
    __nv_bfloat16* sW2h = (__nv_bfloat16*)smraw;     // [128][136]
    __nv_bfloat16* sWdh = sW2h + 17408;              // [96][136]
    __nv_bfloat16* sUh  = sWdh + 13056;              // [96][136]
    __nv_bfloat16* sFdh = sUh;                       // alias (disjoint lifetime)
    float* sS   = (float*)(sUh + 13056);             // [24][30]
    float* sC   = sS  + 720;
    float* sLat = sC  + 720;                         // [128]

    int tx = threadIdx.x;
    int warp = tx>>5, lane = tx&31;
    int gq = lane>>2, tg = lane&3;
    int wx = warp&3, wy = warp>>2;
    int n0 = wx*32, m0 = wy*48;
    int row16 = lane & 15;
    int half8 = (lane & 16) ? 8 : 0;

    // ---- per-layer weights staged ONCE per CTA ----
    {
        const uint4* s2 = (const uint4*)&d_W2bf[l*128*136];
        uint4* t2 = (uint4*)sW2h;
        for (int i=tx; i<128*136/8; i+=256) t2[i] = s2[i];
        const uint4* sd = (const uint4*)&d_Wdbf[l*96*136];
        uint4* td = (uint4*)sWdh;
        for (int i=tx; i<64*136/8; i+=256) td[i] = sd[i];          // rows 0-63
        for (int i=tx; i<8*136/8;  i+=256) td[1496+i] = sd[1496+i]; // rows 88-95 zero
    }
    float rb2[8];
    #pragma unroll
    for (int nt=0;nt<4;nt++)
        #pragma unroll
        for (int qq=0;qq<2;qq++)
            rb2[nt*2+qq] = eb2[l*Hd + n0 + nt*8 + tg*2 + qq];

    for (int gr = blockIdx.x; gr < Gn; gr += gridDim.x){
        // ---- per-graph staging ----
        for (int idx=tx; idx<24*Hd; idx+=256){
            int j = idx>>7, c = idx&127;
            sWdh[(64+j)*136 + c] = __float2bfloat16_rn(d_Q[gr*24*Hd + idx]);
        }
        for (int idx=tx; idx<720; idx+=256){
            sS[idx] = d_ts[gr*720 + idx];
            sC[idx] = d_tc[gr*720 + idx];
        }
        if (tx < 128){
            float acc = eb1[l*Hd + tx];
            const float* wc = ew1 + (l*EINW + 256)*Hd;
            #pragma unroll
            for (int k=0;k<9;k++) acc += d_latips[gr*9+k] * wc[k*Hd + tx];
            sLat[tx] = acc;
        }
        __syncthreads();

        for (int it=0; it<6; ++it){
            int i0 = it*4;
            // ---- build Fd: trig pairs (cols 0-59) ----
            for (int idx=tx; idx<96*30; idx+=256){
                int e = idx/30; int df = idx - e*30;
                int s = e/24; int j = e - s*24; int i = i0+s;
                float sj = sS[j*30+df], cj = sC[j*30+df];
                float si = sS[i*30+df], ci = sC[i*30+df];
                sFdh[e*136 + df]      = __float2bfloat16_rn(sj*ci - cj*si);
                sFdh[e*136 + 30 + df] = __float2bfloat16_rn(cj*ci + sj*si);
            }
            // ---- Fd one-hot block (cols 60-95) ----
            for (int idx=tx; idx<96*36; idx+=256){
                int e = idx/36; int k = 60 + (idx - e*36);
                int s = e/24; int j = e - s*24;
                float v = (k == 60+s || k == 64+j) ? 1.f : 0.f;
                sFdh[e*136 + k] = __float2bfloat16_rn(v);
            }
            // ---- restage P+latC into sWdh rows 60-63 ----
            for (int idx=tx; idx<4*Hd; idx+=256){
                int s = idx>>7, c = idx&127;
                sWdh[(60+s)*136 + c] =
                    __float2bfloat16_rn(d_P[(gr*24+i0+s)*Hd + c] + sLat[c]);
            }
            __syncthreads();

            // ---- GEMM-A: Fd[96x96] @ Wd_aug[96x128] ----
            float da[3][4][4];
            #pragma unroll
            for (int mt=0;mt<3;mt++)
                #pragma unroll
                for (int nt=0;nt<4;nt++)
                    #pragma unroll
                    for (int q=0;q<4;q++) da[mt][nt][q] = 0.f;
            #pragma unroll
            for (int kk=0;kk<6;kk++){
                int k0 = kk*16;
                unsigned ua[3][4], ub[4][2];
                #pragma unroll
                for (int mt=0;mt<3;mt++)
                    ldsm4(ua[mt][0],ua[mt][1],ua[mt][2],ua[mt][3],
                          &sFdh[(m0+mt*16+row16)*136 + k0 + half8]);
                #pragma unroll
                for (int np=0;np<2;np++){
                    unsigned t0,t1,t2,t3;
                    ldsm4t(t0,t1,t2,t3, &sWdh[(k0+row16)*136 + n0+np*16 + half8]);
                    ub[2*np][0]=t0; ub[2*np][1]=t1;
                    ub[2*np+1][0]=t2; ub[2*np+1][1]=t3;
                }
                #pragma unroll
                for (int mt=0;mt<3;mt++)
                    #pragma unroll
                    for (int nt=0;nt<4;nt++)
                        mma16(da[mt][nt], ua[mt], ub[nt]);
            }
            __syncthreads();   // Fd reads done before U overwrites

            // ---- epilogue A: silu only ----
            #pragma unroll
            for (int mt=0;mt<3;mt++){
                #pragma unroll
                for (int nt=0;nt<4;nt++){
                    int c = n0 + nt*8 + tg*2;
                    #pragma unroll
                    for (int h=0; h<2; h++){
                        int r = m0 + mt*16 + gq + h*8;
                        float v0 = silu_f(da[mt][nt][2*h+0]);
                        float v1 = silu_f(da[mt][nt][2*h+1]);
                        *(unsigned*)&sUh[r*136 + c] = pack_bf2(v0, v1);
                    }
                }
            }
            __syncthreads();

            // ---- GEMM-B: U[96x128] @ W2[128x128] ----
            float de[3][4][4];
            #pragma unroll
            for (int mt=0;mt<3;mt++)
                #pragma unroll
                for (int nt=0;nt<4;nt++)
                    #pragma unroll
                    for (int q=0;q<4;q++) de[mt][nt][q] = 0.f;
            #pragma unroll
            for (int kk=0;kk<8;kk++){
                int k0 = kk*16;
                unsigned ua[3][4], ub[4][2];
                #pragma unroll
                for (int mt=0;mt<3;mt++)
                    ldsm4(ua[mt][0],ua[mt][1],ua[mt][2],ua[mt][3],
                          &sUh[(m0+mt*16+row16)*136 + k0 + half8]);
                #pragma unroll
                for (int np=0;np<2;np++){
                    unsigned t0,t1,t2,t3;
                    ldsm4t(t0,t1,t2,t3, &sW2h[(k0+row16)*136 + n0+np*16 + half8]);
                    ub[2*np][0]=t0; ub[2*np][1]=t1;
                    ub[2*np+1][0]=t2; ub[2*np+1][1]=t3;
                }
                #pragma unroll
                for (int mt=0;mt<3;mt++)
                    #pragma unroll
                    for (int nt=0;nt<4;nt++)
                        mma16(de[mt][nt], ua[mt], ub[nt]);
            }
            // ---- epilogue B: +b2(regs), silu, shuffle scatter-mean ----
            int iA = i0 + wy*2, iB = iA + 1;
            #pragma unroll
            for (int nt=0;nt<4;nt++){
                #pragma unroll
                for (int qq=0;qq<2;qq++){
                    int c = n0 + nt*8 + tg*2 + qq;
                    float b = rb2[nt*2+qq];
                    float s0 = silu_f(de[0][nt][qq]+b) + silu_f(de[0][nt][2+qq]+b)
                             + silu_f(de[1][nt][qq]+b);
                    float s1 = silu_f(de[1][nt][2+qq]+b) + silu_f(de[2][nt][qq]+b)
                             + silu_f(de[2][nt][2+qq]+b);
                    #pragma unroll
                    for (int off=4;off<32;off<<=1){
                        s0 += __shfl_xor_sync(0xffffffffu, s0, off);
                        s1 += __shfl_xor_sync(0xffffffffu, s1, off);
                    }
                    if (gq == 0){
                        d_agg[(gr*24 + iA)*Hd + c] = s0 * (1.0f/24.0f);
                        d_agg[(gr*24 + iB)*Hd + c] = s1 * (1.0f/24.0f);
                    }
                }
            }
            __syncthreads();
        }
    }
}

// ---------------- fused node MLP + next proj (tf32, 2 graphs/CTA, 2 CTA/SM) ---
__global__ void __launch_bounds__(256) node_fused(
    const float* __restrict__ nw1, const float* __restrict__ nb1,
    const float* __restrict__ nw2, const float* __restrict__ nb2,
    const float* __restrict__ ew1, int l, int do_proj)
{
    extern __shared__ __align__(16) unsigned smu[];
    unsigned* sX  = smu;               // [48][260]
    unsigned* sWb = sX + 48*260;       // chunk buffer (8704 u32; holds [64][136] or [32][264])
    unsigned* sY  = sWb + 8704;        // [48][132]
    float* sB = (float*)(sY + 48*132); // b1[128] | b2[128]
    unsigned* sH = sY;                 // proj-phase alias

    int r0g = blockIdx.x*48;           // 2 graphs = 48 rows
    int tx = threadIdx.x;
    int warp = tx>>5, lane = tx&31;
    int gq = lane>>2, tg = lane&3;

    for (int idx=tx; idx<48*256; idx+=256){
        int r = idx>>8, k = idx&255;
        float v = (k<128) ? d_h[(r0g+r)*Hd + k]
                          : d_agg[(r0g+r)*Hd + (k-128)];
        sX[r*260+k] = tf32_rna(v);
    }
    if (tx < 128){ sB[tx] = nb1[l*Hd+tx]; sB[128+tx] = nb2[l*Hd+tx]; }

    // ---- GEMM1: X[48x256] @ W1[256x128], W1 in 4 chunks of 64 k-rows ----
    const float* W1 = nw1 + l*256*Hd;
    float a1[3][2][4];
    #pragma unroll
    for (int mt=0;mt<3;mt++)
        #pragma unroll
        for (int nt=0;nt<2;nt++)
            #pragma unroll
            for (int q=0;q<4;q++) a1[mt][nt][q] = 0.f;

    for (int kc=0; kc<4; kc++){
        for (int idx=tx; idx<64*Hd; idx+=256){
            int k = idx>>7, c = idx&127;
            sWb[k*136+c] = tf32_rna(W1[(kc*64+k)*Hd + c]);
        }
        __syncthreads();
        #pragma unroll
        for (int kk=0;kk<8;kk++){
            int ka = kc*64 + kk*8;
            int kb = kk*8;
            unsigned ua[3][4], ub[2][2];
            #pragma unroll
            for (int mt=0;mt<3;mt++){
                int r = mt*16 + gq;
                ua[mt][0] = sX[r*260 + ka+tg];
                ua[mt][1] = sX[(r+8)*260 + ka+tg];
                ua[mt][2] = sX[r*260 + ka+tg+4];
                ua[mt][3] = sX[(r+8)*260 + ka+tg+4];
            }
            #pragma unroll
            for (int nt=0;nt<2;nt++){
                int c = warp*16 + nt*8 + gq;
                ub[nt][0] = sWb[(kb+tg)*136 + c];
                ub[nt][1] = sWb[(kb+tg+4)*136 + c];
            }
            #pragma unroll
            for (int mt=0;mt<3;mt++)
                #pragma unroll
                for (int nt=0;nt<2;nt++)
                    mma8(a1[mt][nt], ua[mt], ub[nt]);
        }
        __syncthreads();
    }

    // epilogue 1 -> tf32 Y
    #pragma unroll
    for (int mt=0;mt<3;mt++){
        #pragma unroll
        for (int nt=0;nt<2;nt++){
            int c = warp*16 + nt*8 + tg*2;
            #pragma unroll
            for (int h=0;h<2;h++){
                int r = mt*16 + gq + h*8;
                sY[r*132 + c]   = tf32_rna(silu_f(a1[mt][nt][2*h+0] + sB[c]));
                sY[r*132 + c+1] = tf32_rna(silu_f(a1[mt][nt][2*h+1] + sB[c+1]));
            }
        }
    }

    // ---- GEMM2: Y[48x128] @ W2[128x128], 2 chunks of 64 ----
    const float* W2 = nw2 + l*Hd*Hd;
    float a2[3][2][4];
    #pragma unroll
    for (int mt=0;mt<3;mt++)
        #pragma unroll
        for (int nt=0;nt<2;nt++)
            #pragma unroll
            for (int q=0;q<4;q++) a2[mt][nt][q] = 0.f;

    for (int kc=0; kc<2; kc++){
        __syncthreads();   // sY writes (kc=0) / prior chunk reads complete
        for (int idx=tx; idx<64*Hd; idx+=256){
            int k = idx>>7, c = idx&127;
            sWb[k*136+c] = tf32_rna(W2[(kc*64+k)*Hd + c]);
        }
        __syncthreads();
        #pragma unroll
        for (int kk=0;kk<8;kk++){
            int ka = kc*64 + kk*8;
            int kb = kk*8;
            unsigned ua[3][4], ub[2][2];
            #pragma unroll
            for (int mt=0;mt<3;mt++){
                int r = mt*16 + gq;
                ua[mt][0] = sY[r*132 + ka+tg];
                ua[mt][1] = sY[(r+8)*132 + ka+tg];
                ua[mt][2] = sY[r*132 + ka+tg+4];
                ua[mt][3] = sY[(r+8)*132 + ka+tg+4];
            }
            #pragma unroll
            for (int nt=0;nt<2;nt++){
                int c = warp*16 + nt*8 + gq;
                ub[nt][0] = sWb[(kb+tg)*136 + c];
                ub[nt][1] = sWb[(kb+tg+4)*136 + c];
            }
            #pragma unroll
            for (int mt=0;mt<3;mt++)
                #pragma unroll
                for (int nt=0;nt<2;nt++)
                    mma8(a2[mt][nt], ua[mt], ub[nt]);
        }
    }
    __syncthreads();   // all Y reads done before sH overwrites (proj phase)

    // epilogue 2: residual -> global h (+ keep for proj)
    float nh[3][2][4];
    #pragma unroll
    for (int mt=0;mt<3;mt++){
        #pragma unroll
        for (int nt=0;nt<2;nt++){
            int c = warp*16 + nt*8 + tg*2;
            #pragma unroll
            for (int h=0;h<2;h++){
                int r = mt*16 + gq + h*8;
                float o0 = silu_f(a2[mt][nt][2*h+0] + sB[128+c]);
                float o1 = silu_f(a2[mt][nt][2*h+1] + sB[128+c+1]);
                float2* p = (float2*)&d_h[(r0g+r)*Hd + c];
                float2 old = *p;
                old.x += o0; old.y += o1;
                *p = old;
                nh[mt][nt][2*h+0] = old.x;
                nh[mt][nt][2*h+1] = old.y;
            }
        }
    }
    if (!do_proj) return;

    // ---- proj phase (layer l+1): h[48x128] @ Wab[128x256], 4 chunks of 32 ----
    #pragma unroll
    for (int mt=0;mt<3;mt++){
        #pragma unroll
        for (int nt=0;nt<2;nt++){
            int c = warp*16 + nt*8 + tg*2;
            #pragma unroll
            for (int h=0;h<2;h++){
                int r = mt*16 + gq + h*8;
                sH[r*132 + c]   = tf32_rna(nh[mt][nt][2*h+0]);
                sH[r*132 + c+1] = tf32_rna(nh[mt][nt][2*h+1]);
            }
        }
    }
    int lp = l+1;
    float accp[3][4][4];
    #pragma unroll
    for (int mt=0;mt<3;mt++)
        #pragma unroll
        for (int nt=0;nt<4;nt++)
            #pragma unroll
            for (int q=0;q<4;q++) accp[mt][nt][q] = 0.f;

    for (int kc=0; kc<4; kc++){
        __syncthreads();   // sH writes (kc=0) / prior chunk reads complete
        for (int idx=tx; idx<32*256; idx+=256){
            int k = idx>>8, n = idx&255;
            float v = (n<128) ? ew1[(lp*EINW + kc*32 + k)*Hd + n]
                              : ew1[(lp*EINW + 128 + kc*32 + k)*Hd + (n-128)];
            sWb[k*264+n] = tf32_rna(v);
        }
        __syncthreads();
        #pragma unroll
        for (int kk=0;kk<4;kk++){
            int ka = kc*32 + kk*8;
            int kb = kk*8;
            unsigned ua[3][4], ub[4][2];
            #pragma unroll
            for (int mt=0;mt<3;mt++){
                int r = mt*16 + gq;
                ua[mt][0] = sH[r*132 + ka+tg];
                ua[mt][1] = sH[(r+8)*132 + ka+tg];
                ua[mt][2] = sH[r*132 + ka+tg+4];
                ua[mt][3] = sH[(r+8)*132 + ka+tg+4];
            }
            #pragma unroll
            for (int nt=0;nt<4;nt++){
                int c = warp*32 + nt*8 + gq;
                ub[nt][0] = sWb[(kb+tg)*264 + c];
                ub[nt][1] = sWb[(kb+tg+4)*264 + c];
            }
            #pragma unroll
            for (int mt=0;mt<3;mt++)
                #pragma unroll
                for (int nt=0;nt<4;nt++)
                    mma8(accp[mt][nt], ua[mt], ub[nt]);
        }
    }
    #pragma unroll
    for (int mt=0;mt<3;mt++){
        #pragma unroll
        for (int nt=0;nt<4;nt++){
            int c = warp*32 + nt*8 + tg*2;
            #pragma unroll
            for (int h=0;h<2;h++){
                int r = mt*16 + gq + h*8;
                float2 v = make_float2(accp[mt][nt][2*h+0], accp[mt][nt][2*h+1]);
                if (c < 128) *(float2*)&d_P[(r0g+r)*Hd + c] = v;
                else         *(float2*)&d_Q[(r0g+r)*Hd + (c-128)] = v;
            }
        }
    }
}

// ---------------- final heads -------------------------------------------------
__global__ void __launch_bounds__(128) final_kernel(
    const float* __restrict__ lat, const float* __restrict__ cw,
    const float* __restrict__ lw, float* __restrict__ out)
{
    __shared__ float sh[24*Hd];
    __shared__ float sgf[Hd];
    __shared__ float smid[9];
    __shared__ float scw[Hd*3];
    int g = blockIdx.x; int tx = threadIdx.x;
    for (int idx=tx; idx<24*Hd; idx+=128) sh[idx] = d_h[g*24*Hd + idx];
    for (int idx=tx; idx<Hd*3; idx+=128) scw[idx] = cw[idx];
    __syncthreads();
    {
        float acc = 0.f;
        #pragma unroll
        for (int a=0;a<24;a++) acc += sh[a*Hd + tx];
        sgf[tx] = acc * (1.0f/24.0f);
    }
    if (tx < 72){
        int n = tx/3; int dd = tx - n*3;
        float s = 0.f;
        #pragma unroll 4
        for (int k=0;k<Hd;k++) s += sh[n*Hd+k]*scw[k*3+dd];
        out[Gn*9 + (g*24+n)*3 + dd] = s;
    }
    __syncthreads();
    if (tx < 9){
        float s = 0.f;
        #pragma unroll 4
        for (int k=0;k<Hd;k++) s += sgf[k]*lw[k*9+tx];
        smid[tx] = s;
    }
    __syncthreads();
    if (tx < 9){
        int r = tx/3; int sc = tx - r*3;
        const float* Lg = lat + g*9;
        out[g*9+tx] = smid[r*3+0]*Lg[0+sc] + smid[r*3+1]*Lg[3+sc]
                    + smid[r*3+2]*Lg[6+sc];
    }
}

// ---------------- launch ------------------------------------------------------
extern "C" void kernel_launch(void* const* d_in, const int* in_sizes, int n_in,
                              void* d_out, int out_size)
{
    const float* t          = (const float*)d_in[0];
    const int*   atom_types = (const int*)  d_in[1];
    const float* frac       = (const float*)d_in[2];
    const float* lattices   = (const float*)d_in[3];
    const int*   node2graph = (const int*)  d_in[5];
    const float* xrd        = (const float*)d_in[6];
    const float* emb        = (const float*)d_in[7];
    const float* latent_w   = (const float*)d_in[8];
    const float* latent_b   = (const float*)d_in[9];
    const float* edge_w1    = (const float*)d_in[10];
    const float* edge_b1    = (const float*)d_in[11];
    const float* edge_w2    = (const float*)d_in[12];
    const float* edge_b2    = (const float*)d_in[13];
    const float* node_w1    = (const float*)d_in[14];
    const float* node_b1    = (const float*)d_in[15];
    const float* node_w2    = (const float*)d_in[16];
    const float* node_b2    = (const float*)d_in[17];
    const float* coord_w    = (const float*)d_in[18];
    const float* lattice_w  = (const float*)d_in[19];
    float* out = (float*)d_out;

    cudaFuncSetAttribute(edge_kernel,
        cudaFuncAttributeMaxDynamicSharedMemorySize, EDGE_SMEM_BYTES);
    cudaFuncSetAttribute(nodeproj_tc,
        cudaFuncAttributeMaxDynamicSharedMemorySize, NP_SMEM_BYTES);
    cudaFuncSetAttribute(node_fused,
        cudaFuncAttributeMaxDynamicSharedMemorySize, NF_SMEM_BYTES);

    trig_kernel<<<(NN*30 + 255)/256, 256>>>(frac);
    latent_kernel<<<NN/48, 256>>>(t, atom_types, node2graph, xrd,
                                  emb, latent_w, latent_b);
    latips_kernel<<<(Gn*9 + 255)/256, 256>>>(lattices);
    wconv_kernel<<<(NLAYER*128*136 + 255)/256, 256>>>(edge_w1, edge_w2);

    nodeproj_tc<<<Gn/4, 256, NP_SMEM_BYTES>>>(edge_w1, 0);
    for (int l=0; l<NLAYER; ++l){
        edge_kernel<<<Gn/2, 256, EDGE_SMEM_BYTES>>>(edge_w1, edge_b1, edge_b2, l);
        node_fused<<<Gn/2, 256, NF_SMEM_BYTES>>>(node_w1, node_b1,
                                                 node_w2, node_b2,
                                                 edge_w1, l, l < NLAYER-1);
    }

    final_kernel<<<Gn, 128>>>(lattices, coord_w, lattice_w, out);
}